// round 3
// baseline (speedup 1.0000x reference)
#include <cuda_runtime.h>
#include <cuda_bf16.h>
#include <cstdint>
#include <cstddef>

#define SEQ 2048
#define BZ 16
#define DIM 1024
#define MROWS (SEQ*BZ)
#define NKC 16
#define TILEB 16384
#define STB (4*TILEB)
#define SMEM_DYN (3*STB)

__device__ __align__(256) __nv_bfloat16 g_Xhi[(size_t)MROWS*DIM];
__device__ __align__(256) __nv_bfloat16 g_Xlo[(size_t)MROWS*DIM];
__device__ __align__(256) __nv_bfloat16 g_Wbhi[(size_t)DIM*DIM];
__device__ __align__(256) __nv_bfloat16 g_Wblo[(size_t)DIM*DIM];
__device__ __align__(256) __nv_bfloat16 g_Wthi[(size_t)16*DIM*DIM];
__device__ __align__(256) __nv_bfloat16 g_Wtlo[(size_t)16*DIM*DIM];
__device__ __align__(256) __nv_bfloat16 g_Hhi[(size_t)MROWS*DIM];
__device__ __align__(256) __nv_bfloat16 g_Hlo[(size_t)MROWS*DIM];

__device__ __forceinline__ uint32_t smem_u32(const void* p){
    uint32_t a;
    asm("{ .reg .u64 t; cvta.to.shared.u64 t, %1; cvt.u32.u64 %0, t; }" : "=r"(a) : "l"(p));
    return a;
}
#define SWZ(o) ((o) ^ (((o) >> 3) & 0x70))

__device__ __forceinline__ void cp_async16(uint32_t s, const void* g){
    asm volatile("cp.async.cg.shared.global [%0], [%1], 16;" :: "r"(s), "l"(g));
}
#define CP_COMMIT() asm volatile("cp.async.commit_group;" ::: "memory")
#define CP_WAIT1()  asm volatile("cp.async.wait_group 1;" ::: "memory")
#define CP_WAIT0()  asm volatile("cp.async.wait_group 0;" ::: "memory")

__device__ __forceinline__ void ldsm4(uint32_t* r, uint32_t addr){
    asm volatile("ldmatrix.sync.aligned.m8n8.x4.shared.b16 {%0,%1,%2,%3}, [%4];"
        : "=r"(r[0]), "=r"(r[1]), "=r"(r[2]), "=r"(r[3]) : "r"(addr));
}
__device__ __forceinline__ void mma16816(float* d, const uint32_t* a, const uint32_t* b){
    asm volatile("mma.sync.aligned.m16n8k16.row.col.f32.bf16.bf16.f32 "
        "{%0,%1,%2,%3}, {%4,%5,%6,%7}, {%8,%9}, {%0,%1,%2,%3};"
        : "+f"(d[0]), "+f"(d[1]), "+f"(d[2]), "+f"(d[3])
        : "r"(a[0]), "r"(a[1]), "r"(a[2]), "r"(a[3]), "r"(b[0]), "r"(b[1]));
}

// ---------------- prologue kernels ----------------
__device__ __forceinline__ void split_pack4(float4 v, uint2& ph, uint2& pl){
    float f[4] = {v.x, v.y, v.z, v.w};
    uint32_t h[4], l[4];
#pragma unroll
    for (int k = 0; k < 4; k++){
        __nv_bfloat16 hb = __float2bfloat16(f[k]);
        __nv_bfloat16 lb = __float2bfloat16(f[k] - __bfloat162float(hb));
        h[k] = (uint32_t)__bfloat16_as_ushort(hb);
        l[k] = (uint32_t)__bfloat16_as_ushort(lb);
    }
    ph.x = h[0] | (h[1] << 16); ph.y = h[2] | (h[3] << 16);
    pl.x = l[0] | (l[1] << 16); pl.y = l[2] | (l[3] << 16);
}
__global__ void split_x_kernel(const float* __restrict__ in){
    size_t i = (size_t)blockIdx.x * 256 + threadIdx.x;
    float4 v = reinterpret_cast<const float4*>(in)[i];
    uint2 ph, pl; split_pack4(v, ph, pl);
    reinterpret_cast<uint2*>(g_Xhi)[i] = ph;
    reinterpret_cast<uint2*>(g_Xlo)[i] = pl;
}
__global__ void split_wb_kernel(const float* __restrict__ in){
    size_t i = (size_t)blockIdx.x * 256 + threadIdx.x;
    float4 v = reinterpret_cast<const float4*>(in)[i];
    uint2 ph, pl; split_pack4(v, ph, pl);
    reinterpret_cast<uint2*>(g_Wbhi)[i] = ph;
    reinterpret_cast<uint2*>(g_Wblo)[i] = pl;
}
// W[l][d][e'] fp32 -> Wt[l][e'][d] bf16 hi/lo
__global__ void transpose_split_kernel(const float* __restrict__ W){
    __shared__ float t[32][33];
    int l  = blockIdx.z;
    int d0 = blockIdx.x * 32;
    int p0 = blockIdx.y * 32;
    int tx = threadIdx.x, ty = threadIdx.y;
    const float* src = W + ((size_t)l << 20);
#pragma unroll
    for (int j = 0; j < 32; j += 8)
        t[ty + j][tx] = src[(size_t)(d0 + ty + j) * DIM + p0 + tx];
    __syncthreads();
#pragma unroll
    for (int j = 0; j < 32; j += 8){
        float v = t[tx][ty + j];   // = W[l][d0+tx][p0+ty+j]
        size_t o = ((size_t)l << 20) + (size_t)(p0 + ty + j) * DIM + d0 + tx;
        __nv_bfloat16 hb = __float2bfloat16(v);
        g_Wthi[o] = hb;
        g_Wtlo[o] = __float2bfloat16(v - __bfloat162float(hb));
    }
}

// ---------------- GEMM via mma.sync (bf16 hi/lo 3-pass) ----------------
// MODE 0: H = x @ W_base^T + b_base  -> g_Hhi/g_Hlo in [b][s][e]
// MODE 1: out[s][b][e'] = Hp[b] @ Wt[id_b]^T + bias[id_b]
template<int MODE>
__global__ void __launch_bounds__(256,1) gemm_kernel(
    const __nv_bfloat16* __restrict__ Abase_hi, const __nv_bfloat16* __restrict__ Abase_lo,
    const __nv_bfloat16* __restrict__ Bbase_hi, const __nv_bfloat16* __restrict__ Bbase_lo,
    const float* __restrict__ addvec,
    const int* __restrict__ lang_ids, const int* __restrict__ dict_len, int has_dict,
    float* __restrict__ out)
{
    extern __shared__ char smem_raw[];
    uint32_t tiles = smem_u32(smem_raw);
    int tid = threadIdx.x, wid = tid >> 5, lid = tid & 31;
    int wm = wid & 1, wn = wid >> 1;          // 2 x 4 warp grid
    int nt = blockIdx.x, mt = blockIdx.y, bb = blockIdx.z;

    const __nv_bfloat16 *Ahi, *Alo, *Bhi, *Blo;
    int id = 0;
    if (MODE == 0){
        Ahi = Abase_hi + (size_t)mt*128*DIM;  Alo = Abase_lo + (size_t)mt*128*DIM;
        Bhi = Bbase_hi + (size_t)nt*128*DIM;  Blo = Bbase_lo + (size_t)nt*128*DIM;
    } else {
        int dl = has_dict ? dict_len[0] : 32000;
        id = dl - 1 - lang_ids[bb];
        size_t ao = ((size_t)bb*SEQ + (size_t)mt*128)*DIM;
        Ahi = Abase_hi + ao;  Alo = Abase_lo + ao;
        size_t bo = ((size_t)id*DIM + (size_t)nt*128)*DIM;
        Bhi = Bbase_hi + bo;  Blo = Bbase_lo + bo;
    }
    const __nv_bfloat16* srcs[4] = {Ahi, Alo, Bhi, Blo};

    auto load_stage = [&](int kc, int st){
        uint32_t sb = tiles + st * STB;
#pragma unroll
        for (int t = 0; t < 4; t++){
            const char* g = (const char*)srcs[t] + (size_t)kc * 128;
            uint32_t d0 = sb + t * TILEB;
#pragma unroll
            for (int i = 0; i < 4; i++){
                int idx = tid + 256 * i;
                int row = idx >> 3, seg = idx & 7;
                cp_async16(d0 + SWZ(row*128 + seg*16), g + (size_t)row*2048 + seg*16);
            }
        }
        CP_COMMIT();
    };

    float acc[4][4][4];
#pragma unroll
    for (int a = 0; a < 4; a++)
#pragma unroll
        for (int b = 0; b < 4; b++)
#pragma unroll
            for (int c = 0; c < 4; c++) acc[a][b][c] = 0.f;

    // ldmatrix per-thread base coordinates
    int a_row = wm*64 + (lid & 7) + ((lid >> 3) & 1) * 8;  // + mi*16
    int a_sg  = (lid >> 4);                                 // + ks*2
    int b_row = wn*32 + (lid & 7) + (lid >> 4) * 8;         // + ni2*16
    int b_sg  = (lid >> 3) & 1;                             // + ks*2

    load_stage(0, 0); load_stage(1, 1);

    for (int kc = 0; kc < NKC; kc++){
        int st = kc - (kc/3)*3;
        if (kc == NKC-1) { CP_WAIT0(); } else { CP_WAIT1(); }
        __syncthreads();
        if (kc + 2 < NKC) load_stage(kc + 2, (kc+2) - ((kc+2)/3)*3);

        uint32_t sA  = tiles + st * STB;
        uint32_t sAl = sA + TILEB, sB = sA + 2*TILEB, sBl = sA + 3*TILEB;
#pragma unroll
        for (int ks = 0; ks < 4; ks++){
            uint32_t ah[4][4], al[4][4], bh[2][4], bl[2][4];
#pragma unroll
            for (int mi = 0; mi < 4; mi++){
                uint32_t off = SWZ((a_row + mi*16)*128 + (ks*2 + a_sg)*16);
                ldsm4(ah[mi], sA  + off);
                ldsm4(al[mi], sAl + off);
            }
#pragma unroll
            for (int ni2 = 0; ni2 < 2; ni2++){
                uint32_t off = SWZ((b_row + ni2*16)*128 + (ks*2 + b_sg)*16);
                ldsm4(bh[ni2], sB  + off);
                ldsm4(bl[ni2], sBl + off);
            }
#pragma unroll
            for (int mi = 0; mi < 4; mi++)
#pragma unroll
                for (int ni = 0; ni < 4; ni++){
                    const uint32_t* bhp = &bh[ni>>1][(ni&1)*2];
                    const uint32_t* blp = &bl[ni>>1][(ni&1)*2];
                    mma16816(acc[mi][ni], ah[mi], bhp);
                    mma16816(acc[mi][ni], ah[mi], blp);
                    mma16816(acc[mi][ni], al[mi], bhp);
                }
        }
    }

    // epilogue
#pragma unroll
    for (int ni = 0; ni < 4; ni++){
        int col = nt*128 + wn*32 + ni*8 + (lid & 3)*2;
        float av0, av1;
        if (MODE == 0){ av0 = addvec[col]; av1 = addvec[col+1]; }
        else { av0 = addvec[(size_t)id*DIM + col]; av1 = addvec[(size_t)id*DIM + col + 1]; }
#pragma unroll
        for (int mi = 0; mi < 4; mi++){
#pragma unroll
            for (int h = 0; h < 2; h++){
                int gm = mt*128 + wm*64 + mi*16 + (lid >> 2) + h*8;
                float v0 = acc[mi][ni][h*2]   + av0;
                float v1 = acc[mi][ni][h*2+1] + av1;
                if (MODE == 0){
                    int b = gm & 15, s = gm >> 4;
                    size_t o = ((size_t)b*SEQ + s)*DIM + col;
                    __nv_bfloat16 h0 = __float2bfloat16(v0);
                    __nv_bfloat16 h1 = __float2bfloat16(v1);
                    __nv_bfloat162 hv; hv.x = h0; hv.y = h1;
                    __nv_bfloat162 lv;
                    lv.x = __float2bfloat16(v0 - __bfloat162float(h0));
                    lv.y = __float2bfloat16(v1 - __bfloat162float(h1));
                    *reinterpret_cast<__nv_bfloat162*>(&g_Hhi[o]) = hv;
                    *reinterpret_cast<__nv_bfloat162*>(&g_Hlo[o]) = lv;
                } else {
                    size_t o = ((size_t)gm*BZ + bb)*DIM + col;
                    float2 f2; f2.x = v0; f2.y = v1;
                    *reinterpret_cast<float2*>(&out[o]) = f2;
                }
            }
        }
    }
}

extern "C" void kernel_launch(void* const* d_in, const int* in_sizes, int n_in,
                              void* d_out, int out_size) {
    const float* x      = (const float*)d_in[0];
    const int*   lids   = (const int*)d_in[1];
    const float* W_base = (const float*)d_in[2];
    const float* b_base = (const float*)d_in[3];
    const float* W      = (const float*)d_in[4];
    const float* bias   = (const float*)d_in[5];
    const int*   dlen   = (n_in > 6) ? (const int*)d_in[6] : nullptr;
    int has_dict = (n_in > 6) ? 1 : 0;
    float* out = (float*)d_out;

    cudaFuncSetAttribute(gemm_kernel<0>, cudaFuncAttributeMaxDynamicSharedMemorySize, SMEM_DYN);
    cudaFuncSetAttribute(gemm_kernel<1>, cudaFuncAttributeMaxDynamicSharedMemorySize, SMEM_DYN);

    split_x_kernel<<<(size_t)MROWS*DIM/4/256, 256>>>(x);
    split_wb_kernel<<<DIM*DIM/4/256, 256>>>(W_base);
    {
        dim3 g(32, 32, 16), b(32, 8);
        transpose_split_kernel<<<g, b>>>(W);
    }

    __nv_bfloat16 *Xhi, *Xlo, *Wbhi, *Wblo, *Wthi, *Wtlo, *Hhi, *Hlo;
    cudaGetSymbolAddress((void**)&Xhi,  g_Xhi);
    cudaGetSymbolAddress((void**)&Xlo,  g_Xlo);
    cudaGetSymbolAddress((void**)&Wbhi, g_Wbhi);
    cudaGetSymbolAddress((void**)&Wblo, g_Wblo);
    cudaGetSymbolAddress((void**)&Wthi, g_Wthi);
    cudaGetSymbolAddress((void**)&Wtlo, g_Wtlo);
    cudaGetSymbolAddress((void**)&Hhi,  g_Hhi);
    cudaGetSymbolAddress((void**)&Hlo,  g_Hlo);

    {
        dim3 g(8, 256, 1), b(256);
        gemm_kernel<0><<<g, b, SMEM_DYN>>>(Xhi, Xlo, Wbhi, Wblo, b_base,
                                           lids, dlen, has_dict, nullptr);
    }
    {
        dim3 g(8, 16, 16), b(256);
        gemm_kernel<1><<<g, b, SMEM_DYN>>>(Hhi, Hlo, Wthi, Wtlo, bias,
                                           lids, dlen, has_dict, out);
    }
}

// round 4
// speedup vs baseline: 1.2081x; 1.2081x over previous
#include <cuda_runtime.h>
#include <cuda_bf16.h>
#include <cstdint>
#include <cstddef>

#define SEQ 2048
#define BZ 16
#define DIM 1024
#define MROWS (SEQ*BZ)
#define NKC 16
#define TILEB 16384
#define STB (4*TILEB)
#define SMEM_DYN (3*STB)

__device__ __align__(256) __nv_bfloat16 g_Xhi[(size_t)MROWS*DIM];
__device__ __align__(256) __nv_bfloat16 g_Xlo[(size_t)MROWS*DIM];
__device__ __align__(256) __nv_bfloat16 g_Wthi[(size_t)16*DIM*DIM];   // W[l]^T : [l][e'][e]
__device__ __align__(256) __nv_bfloat16 g_Wtlo[(size_t)16*DIM*DIM];
__device__ __align__(256) __nv_bfloat16 g_Wbthi[(size_t)DIM*DIM];     // W_base^T : [d][e]
__device__ __align__(256) __nv_bfloat16 g_Wbtlo[(size_t)DIM*DIM];
__device__ __align__(256) __nv_bfloat16 g_Bchi[(size_t)16*DIM*DIM];   // Bt[l][e'][d] = (W_base^T W[l])^T
__device__ __align__(256) __nv_bfloat16 g_Bclo[(size_t)16*DIM*DIM];
__device__ __align__(256) float g_bc[16*DIM];

__device__ __forceinline__ uint32_t smem_u32(const void* p){
    uint32_t a;
    asm("{ .reg .u64 t; cvta.to.shared.u64 t, %1; cvt.u32.u64 %0, t; }" : "=r"(a) : "l"(p));
    return a;
}
#define SWZ(o) ((o) ^ (((o) >> 3) & 0x70))

__device__ __forceinline__ void cp_async16(uint32_t s, const void* g){
    asm volatile("cp.async.cg.shared.global [%0], [%1], 16;" :: "r"(s), "l"(g));
}
#define CP_COMMIT() asm volatile("cp.async.commit_group;" ::: "memory")
#define CP_WAIT1()  asm volatile("cp.async.wait_group 1;" ::: "memory")
#define CP_WAIT0()  asm volatile("cp.async.wait_group 0;" ::: "memory")

__device__ __forceinline__ void ldsm4(uint32_t* r, uint32_t addr){
    asm volatile("ldmatrix.sync.aligned.m8n8.x4.shared.b16 {%0,%1,%2,%3}, [%4];"
        : "=r"(r[0]), "=r"(r[1]), "=r"(r[2]), "=r"(r[3]) : "r"(addr));
}
__device__ __forceinline__ void mma16816(float* d, const uint32_t* a, const uint32_t* b){
    asm volatile("mma.sync.aligned.m16n8k16.row.col.f32.bf16.bf16.f32 "
        "{%0,%1,%2,%3}, {%4,%5,%6,%7}, {%8,%9}, {%0,%1,%2,%3};"
        : "+f"(d[0]), "+f"(d[1]), "+f"(d[2]), "+f"(d[3])
        : "r"(a[0]), "r"(a[1]), "r"(a[2]), "r"(a[3]), "r"(b[0]), "r"(b[1]));
}

// ---------------- prologue kernels ----------------
__device__ __forceinline__ void split_pack4(float4 v, uint2& ph, uint2& pl){
    float f[4] = {v.x, v.y, v.z, v.w};
    uint32_t h[4], l[4];
#pragma unroll
    for (int k = 0; k < 4; k++){
        __nv_bfloat16 hb = __float2bfloat16(f[k]);
        __nv_bfloat16 lb = __float2bfloat16(f[k] - __bfloat162float(hb));
        h[k] = (uint32_t)__bfloat16_as_ushort(hb);
        l[k] = (uint32_t)__bfloat16_as_ushort(lb);
    }
    ph.x = h[0] | (h[1] << 16); ph.y = h[2] | (h[3] << 16);
    pl.x = l[0] | (l[1] << 16); pl.y = l[2] | (l[3] << 16);
}
__global__ void split_x_kernel(const float* __restrict__ in){
    size_t i = (size_t)blockIdx.x * 256 + threadIdx.x;
    float4 v = reinterpret_cast<const float4*>(in)[i];
    uint2 ph, pl; split_pack4(v, ph, pl);
    reinterpret_cast<uint2*>(g_Xhi)[i] = ph;
    reinterpret_cast<uint2*>(g_Xlo)[i] = pl;
}
// src [z][1024][1024] fp32 -> dst [z][c][r] bf16 hi/lo (transpose within each z)
__global__ void transpose_split_kernel(const float* __restrict__ src0,
                                       __nv_bfloat16* __restrict__ dhi,
                                       __nv_bfloat16* __restrict__ dlo){
    __shared__ float t[32][33];
    int l  = blockIdx.z;
    int r0 = blockIdx.x * 32;
    int c0 = blockIdx.y * 32;
    int tx = threadIdx.x, ty = threadIdx.y;
    const float* src = src0 + ((size_t)l << 20);
#pragma unroll
    for (int j = 0; j < 32; j += 8)
        t[ty + j][tx] = src[(size_t)(r0 + ty + j) * DIM + c0 + tx];
    __syncthreads();
#pragma unroll
    for (int j = 0; j < 32; j += 8){
        float v = t[tx][ty + j];   // = src[r0+tx][c0+ty+j]
        size_t o = ((size_t)l << 20) + (size_t)(c0 + ty + j) * DIM + r0 + tx;
        __nv_bfloat16 hb = __float2bfloat16(v);
        dhi[o] = hb;
        dlo[o] = __float2bfloat16(v - __bfloat162float(hb));
    }
}
// bc[l][e'] = bias[l][e'] + sum_e b_base[e] * W[l][e][e']
__global__ void bc_kernel(const float* __restrict__ W, const float* __restrict__ b_base,
                          const float* __restrict__ bias){
    int l = blockIdx.x;
    int e2 = blockIdx.y * 128 + threadIdx.x;
    const float* Wl = W + ((size_t)l << 20);
    float s = 0.f;
    for (int e = 0; e < DIM; e++) s += b_base[e] * Wl[(size_t)e * DIM + e2];
    g_bc[l * DIM + e2] = s + bias[(size_t)l * DIM + e2];
}

// ---------------- GEMM via mma.sync (bf16 hi/lo 3-pass) ----------------
// MODE 0 (precompute): Bt[l] = Wt[l] @ Wbt^T  (m=e', n=d, k=e) -> split-store g_Bchi/lo
// MODE 1 (main): out[s][bb][e'] = x[:,bb,:] @ Bt[id]^T + bc[id]
template<int MODE>
__global__ void __launch_bounds__(256,1) gemm_kernel(
    const __nv_bfloat16* __restrict__ Abase_hi, const __nv_bfloat16* __restrict__ Abase_lo,
    const __nv_bfloat16* __restrict__ Bbase_hi, const __nv_bfloat16* __restrict__ Bbase_lo,
    const float* __restrict__ addvec,
    const int* __restrict__ lang_ids, const int* __restrict__ dict_len, int has_dict,
    float* __restrict__ out)
{
    extern __shared__ char smem_raw[];
    uint32_t tiles = smem_u32(smem_raw);
    int tid = threadIdx.x, wid = tid >> 5, lid = tid & 31;
    int wm = wid & 1, wn = wid >> 1;          // 2 x 4 warp grid
    int nt = blockIdx.x, mt = blockIdx.y, zb = blockIdx.z;

    const __nv_bfloat16 *Ahi, *Alo, *Bhi, *Blo;
    int id = 0;
    if (MODE == 0){
        size_t ao = ((size_t)zb << 20) + (size_t)mt*128*DIM;
        Ahi = Abase_hi + ao;  Alo = Abase_lo + ao;
        Bhi = Bbase_hi + (size_t)nt*128*DIM;  Blo = Bbase_lo + (size_t)nt*128*DIM;
    } else {
        int dl = has_dict ? dict_len[0] : 32000;
        id = dl - 1 - lang_ids[zb];
        size_t ao = (size_t)zb*DIM + (size_t)mt*128*(BZ*DIM);   // rows stride BZ*DIM
        Ahi = Abase_hi + ao;  Alo = Abase_lo + ao;
        size_t bo = ((size_t)id << 20) + (size_t)nt*128*DIM;
        Bhi = Bbase_hi + bo;  Blo = Bbase_lo + bo;
    }
    const __nv_bfloat16* srcs[4] = {Ahi, Alo, Bhi, Blo};
    const size_t RSA = (MODE == 1) ? (size_t)BZ*DIM*2 : (size_t)2048;
    const size_t rstr[4] = {RSA, RSA, 2048, 2048};

    auto load_stage = [&](int kc, int st){
        uint32_t sb = tiles + st * STB;
#pragma unroll
        for (int t = 0; t < 4; t++){
            const char* g = (const char*)srcs[t] + (size_t)kc * 128;
            uint32_t d0 = sb + t * TILEB;
            size_t rs = rstr[t];
#pragma unroll
            for (int i = 0; i < 4; i++){
                int idx = tid + 256 * i;
                int row = idx >> 3, seg = idx & 7;
                cp_async16(d0 + SWZ(row*128 + seg*16), g + (size_t)row*rs + seg*16);
            }
        }
        CP_COMMIT();
    };

    float acc[4][4][4];
#pragma unroll
    for (int a = 0; a < 4; a++)
#pragma unroll
        for (int b = 0; b < 4; b++)
#pragma unroll
            for (int c = 0; c < 4; c++) acc[a][b][c] = 0.f;

    int a_row = wm*64 + (lid & 7) + ((lid >> 3) & 1) * 8;
    int a_sg  = (lid >> 4);
    int b_row = wn*32 + (lid & 7) + (lid >> 4) * 8;
    int b_sg  = (lid >> 3) & 1;

    load_stage(0, 0); load_stage(1, 1);

    for (int kc = 0; kc < NKC; kc++){
        int st = kc - (kc/3)*3;
        if (kc == NKC-1) { CP_WAIT0(); } else { CP_WAIT1(); }
        __syncthreads();
        if (kc + 2 < NKC) load_stage(kc + 2, (kc+2) - ((kc+2)/3)*3);

        uint32_t sA  = tiles + st * STB;
        uint32_t sAl = sA + TILEB, sB = sA + 2*TILEB, sBl = sA + 3*TILEB;
#pragma unroll
        for (int ks = 0; ks < 4; ks++){
            uint32_t ah[4][4], al[4][4], bh[2][4], bl[2][4];
#pragma unroll
            for (int mi = 0; mi < 4; mi++){
                uint32_t off = SWZ((a_row + mi*16)*128 + (ks*2 + a_sg)*16);
                ldsm4(ah[mi], sA  + off);
                ldsm4(al[mi], sAl + off);
            }
#pragma unroll
            for (int ni2 = 0; ni2 < 2; ni2++){
                uint32_t off = SWZ((b_row + ni2*16)*128 + (ks*2 + b_sg)*16);
                ldsm4(bh[ni2], sB  + off);
                ldsm4(bl[ni2], sBl + off);
            }
#pragma unroll
            for (int mi = 0; mi < 4; mi++)
#pragma unroll
                for (int ni = 0; ni < 4; ni++){
                    const uint32_t* bhp = &bh[ni>>1][(ni&1)*2];
                    const uint32_t* blp = &bl[ni>>1][(ni&1)*2];
                    mma16816(acc[mi][ni], ah[mi], bhp);
                    mma16816(acc[mi][ni], ah[mi], blp);
                    mma16816(acc[mi][ni], al[mi], bhp);
                }
        }
    }

    // epilogue
#pragma unroll
    for (int ni = 0; ni < 4; ni++){
        int col = nt*128 + wn*32 + ni*8 + (lid & 3)*2;
        float av0 = 0.f, av1 = 0.f;
        if (MODE == 1){
            av0 = addvec[(size_t)id*DIM + col];
            av1 = addvec[(size_t)id*DIM + col + 1];
        }
#pragma unroll
        for (int mi = 0; mi < 4; mi++){
#pragma unroll
            for (int h = 0; h < 2; h++){
                int gm = mt*128 + wm*64 + mi*16 + (lid >> 2) + h*8;
                float v0 = acc[mi][ni][h*2]   + av0;
                float v1 = acc[mi][ni][h*2+1] + av1;
                if (MODE == 0){
                    size_t o = ((size_t)zb << 20) + (size_t)gm*DIM + col;
                    __nv_bfloat16 h0 = __float2bfloat16(v0);
                    __nv_bfloat16 h1 = __float2bfloat16(v1);
                    __nv_bfloat162 hv; hv.x = h0; hv.y = h1;
                    __nv_bfloat162 lv;
                    lv.x = __float2bfloat16(v0 - __bfloat162float(h0));
                    lv.y = __float2bfloat16(v1 - __bfloat162float(h1));
                    *reinterpret_cast<__nv_bfloat162*>(&g_Bchi[o]) = hv;
                    *reinterpret_cast<__nv_bfloat162*>(&g_Bclo[o]) = lv;
                } else {
                    size_t o = ((size_t)gm*BZ + zb)*DIM + col;
                    float2 f2; f2.x = v0; f2.y = v1;
                    *reinterpret_cast<float2*>(&out[o]) = f2;
                }
            }
        }
    }
}

extern "C" void kernel_launch(void* const* d_in, const int* in_sizes, int n_in,
                              void* d_out, int out_size) {
    const float* x      = (const float*)d_in[0];
    const int*   lids   = (const int*)d_in[1];
    const float* W_base = (const float*)d_in[2];
    const float* b_base = (const float*)d_in[3];
    const float* W      = (const float*)d_in[4];
    const float* bias   = (const float*)d_in[5];
    const int*   dlen   = (n_in > 6) ? (const int*)d_in[6] : nullptr;
    int has_dict = (n_in > 6) ? 1 : 0;
    float* out = (float*)d_out;

    cudaFuncSetAttribute(gemm_kernel<0>, cudaFuncAttributeMaxDynamicSharedMemorySize, SMEM_DYN);
    cudaFuncSetAttribute(gemm_kernel<1>, cudaFuncAttributeMaxDynamicSharedMemorySize, SMEM_DYN);

    __nv_bfloat16 *Xhi, *Xlo, *Wthi, *Wtlo, *Wbthi, *Wbtlo, *Bchi, *Bclo;
    float* bc;
    cudaGetSymbolAddress((void**)&Xhi,   g_Xhi);
    cudaGetSymbolAddress((void**)&Xlo,   g_Xlo);
    cudaGetSymbolAddress((void**)&Wthi,  g_Wthi);
    cudaGetSymbolAddress((void**)&Wtlo,  g_Wtlo);
    cudaGetSymbolAddress((void**)&Wbthi, g_Wbthi);
    cudaGetSymbolAddress((void**)&Wbtlo, g_Wbtlo);
    cudaGetSymbolAddress((void**)&Bchi,  g_Bchi);
    cudaGetSymbolAddress((void**)&Bclo,  g_Bclo);
    cudaGetSymbolAddress((void**)&bc,    g_bc);

    split_x_kernel<<<(size_t)MROWS*DIM/4/256, 256>>>(x);
    {
        dim3 g(32, 32, 16), b(32, 8);
        transpose_split_kernel<<<g, b>>>(W, Wthi, Wtlo);        // Wt[l][e'][e]
    }
    {
        dim3 g(32, 32, 1), b(32, 8);
        transpose_split_kernel<<<g, b>>>(W_base, Wbthi, Wbtlo); // Wbt[d][e]
    }
    bc_kernel<<<dim3(16, 8), 128>>>(W, b_base, bias);

    // Precompute: Bt[l][e'][d] = sum_e Wt[l][e'][e] * Wbt[d][e]
    {
        dim3 g(8, 8, 16), b(256);
        gemm_kernel<0><<<g, b, SMEM_DYN>>>(Wthi, Wtlo, Wbthi, Wbtlo, nullptr,
                                           nullptr, nullptr, 0, nullptr);
    }
    // Main: out[s][bb][e'] = sum_d x[s][bb][d] * Bt[id][e'][d] + bc[id][e']
    {
        dim3 g(8, 16, 16), b(256);
        gemm_kernel<1><<<g, b, SMEM_DYN>>>(Xhi, Xlo, Bchi, Bclo, bc,
                                           lids, dlen, has_dict, out);
    }
}

// round 5
// speedup vs baseline: 1.4946x; 1.2371x over previous
#include <cuda_runtime.h>
#include <cuda_bf16.h>
#include <cstdint>
#include <cstddef>

#define SEQ 2048
#define BZ 16
#define DIM 1024
#define MROWS (SEQ*BZ)
#define NKC 16
#define TILEB 16384
#define STB (4*TILEB)
#define SMEM_DYN (3*STB)

__device__ __align__(256) __nv_bfloat16 g_Xhi[(size_t)MROWS*DIM];
__device__ __align__(256) __nv_bfloat16 g_Xlo[(size_t)MROWS*DIM];
__device__ __align__(256) __nv_bfloat16 g_Wthi[(size_t)16*DIM*DIM];   // W[l]^T : [l][e'][e]
__device__ __align__(256) __nv_bfloat16 g_Wtlo[(size_t)16*DIM*DIM];
__device__ __align__(256) __nv_bfloat16 g_Wbthi[(size_t)DIM*DIM];     // W_base^T : [d][e]
__device__ __align__(256) __nv_bfloat16 g_Wbtlo[(size_t)DIM*DIM];
__device__ __align__(256) __nv_bfloat16 g_Bchi[(size_t)16*DIM*DIM];   // Bt[l][e'][d]
__device__ __align__(256) __nv_bfloat16 g_Bclo[(size_t)16*DIM*DIM];
__device__ __align__(256) float g_bc[16*DIM];

__device__ __forceinline__ uint32_t smem_u32(const void* p){
    uint32_t a;
    asm("{ .reg .u64 t; cvta.to.shared.u64 t, %1; cvt.u32.u64 %0, t; }" : "=r"(a) : "l"(p));
    return a;
}
#define SWZ(o) ((o) ^ (((o) >> 3) & 0x70))

__device__ __forceinline__ void cp_async16(uint32_t s, const void* g){
    asm volatile("cp.async.cg.shared.global [%0], [%1], 16;" :: "r"(s), "l"(g));
}
#define CP_COMMIT() asm volatile("cp.async.commit_group;" ::: "memory")
#define CP_WAIT1()  asm volatile("cp.async.wait_group 1;" ::: "memory")
#define CP_WAIT0()  asm volatile("cp.async.wait_group 0;" ::: "memory")

__device__ __forceinline__ void ldsm4(uint32_t* r, uint32_t addr){
    asm volatile("ldmatrix.sync.aligned.m8n8.x4.shared.b16 {%0,%1,%2,%3}, [%4];"
        : "=r"(r[0]), "=r"(r[1]), "=r"(r[2]), "=r"(r[3]) : "r"(addr));
}
__device__ __forceinline__ void mma16816(float* d, const uint32_t* a, const uint32_t* b){
    asm volatile("mma.sync.aligned.m16n8k16.row.col.f32.bf16.bf16.f32 "
        "{%0,%1,%2,%3}, {%4,%5,%6,%7}, {%8,%9}, {%0,%1,%2,%3};"
        : "+f"(d[0]), "+f"(d[1]), "+f"(d[2]), "+f"(d[3])
        : "r"(a[0]), "r"(a[1]), "r"(a[2]), "r"(a[3]), "r"(b[0]), "r"(b[1]));
}

// language l used by any batch column?
__device__ __forceinline__ bool lang_used(int l, const int* lang_ids, const int* dict_len, int has_dict){
    int dl = has_dict ? dict_len[0] : 32000;
    bool u = false;
#pragma unroll
    for (int i = 0; i < BZ; i++) u |= ((dl - 1 - lang_ids[i]) == l);
    return u;
}

// ---------------- prologue kernels ----------------
__device__ __forceinline__ void split_pack4(float4 v, uint2& ph, uint2& pl){
    float f[4] = {v.x, v.y, v.z, v.w};
    uint32_t h[4], l[4];
#pragma unroll
    for (int k = 0; k < 4; k++){
        __nv_bfloat16 hb = __float2bfloat16(f[k]);
        __nv_bfloat16 lb = __float2bfloat16(f[k] - __bfloat162float(hb));
        h[k] = (uint32_t)__bfloat16_as_ushort(hb);
        l[k] = (uint32_t)__bfloat16_as_ushort(lb);
    }
    ph.x = h[0] | (h[1] << 16); ph.y = h[2] | (h[3] << 16);
    pl.x = l[0] | (l[1] << 16); pl.y = l[2] | (l[3] << 16);
}
__global__ void split_x_kernel(const float* __restrict__ in){
    size_t i = (size_t)blockIdx.x * 256 + threadIdx.x;
    float4 v = reinterpret_cast<const float4*>(in)[i];
    uint2 ph, pl; split_pack4(v, ph, pl);
    reinterpret_cast<uint2*>(g_Xhi)[i] = ph;
    reinterpret_cast<uint2*>(g_Xlo)[i] = pl;
}
// src [z][1024][1024] fp32 -> dst [z][c][r] bf16 hi/lo (transpose within each z)
__global__ void transpose_split_kernel(const float* __restrict__ src0,
                                       __nv_bfloat16* __restrict__ dhi,
                                       __nv_bfloat16* __restrict__ dlo,
                                       const int* __restrict__ lang_ids,
                                       const int* __restrict__ dict_len,
                                       int has_dict, int check){
    int l = blockIdx.z;
    if (check && !lang_used(l, lang_ids, dict_len, has_dict)) return;
    __shared__ float t[32][33];
    int r0 = blockIdx.x * 32;
    int c0 = blockIdx.y * 32;
    int tx = threadIdx.x, ty = threadIdx.y;
    const float* src = src0 + ((size_t)l << 20);
#pragma unroll
    for (int j = 0; j < 32; j += 8)
        t[ty + j][tx] = src[(size_t)(r0 + ty + j) * DIM + c0 + tx];
    __syncthreads();
#pragma unroll
    for (int j = 0; j < 32; j += 8){
        float v = t[tx][ty + j];   // = src[r0+tx][c0+ty+j]
        size_t o = ((size_t)l << 20) + (size_t)(c0 + ty + j) * DIM + r0 + tx;
        __nv_bfloat16 hb = __float2bfloat16(v);
        dhi[o] = hb;
        dlo[o] = __float2bfloat16(v - __bfloat162float(hb));
    }
}
// bc[l][e'] = bias[l][e'] + sum_e b_base[e] * W[l][e][e']   (parallel e-reduction)
__global__ void __launch_bounds__(1024,1) bc_kernel(
    const float* __restrict__ W, const float* __restrict__ b_base,
    const float* __restrict__ bias,
    const int* __restrict__ lang_ids, const int* __restrict__ dict_len, int has_dict){
    int l = blockIdx.x;
    if (!lang_used(l, lang_ids, dict_len, has_dict)) return;
    __shared__ float red[1024];
    int t  = threadIdx.x & 127;          // e2 within chunk
    int es = threadIdx.x >> 7;           // e slice 0..7
    int e2 = blockIdx.y * 128 + t;
    const float* Wl = W + ((size_t)l << 20);
    float s = 0.f;
#pragma unroll 4
    for (int e = es*128; e < es*128 + 128; e++)
        s += b_base[e] * Wl[(size_t)e * DIM + e2];
    red[threadIdx.x] = s;
    __syncthreads();
#pragma unroll
    for (int st = 512; st >= 128; st >>= 1){
        if (threadIdx.x < st) red[threadIdx.x] += red[threadIdx.x + st];
        __syncthreads();
    }
    if (threadIdx.x < 128)
        g_bc[l * DIM + e2] = red[threadIdx.x] + bias[(size_t)l * DIM + e2];
}

// ---------------- GEMM via mma.sync (bf16 hi/lo 3-pass) ----------------
// MODE 0 (precompute): Bt[l] = Wt[l] @ Wbt^T  -> split-store g_Bchi/lo  (skips unused l)
// MODE 1 (main): out[s][bb][e'] = x[:,bb,:] @ Bt[id]^T + bc[id]
template<int MODE>
__global__ void __launch_bounds__(256,1) gemm_kernel(
    const __nv_bfloat16* __restrict__ Abase_hi, const __nv_bfloat16* __restrict__ Abase_lo,
    const __nv_bfloat16* __restrict__ Bbase_hi, const __nv_bfloat16* __restrict__ Bbase_lo,
    const float* __restrict__ addvec,
    const int* __restrict__ lang_ids, const int* __restrict__ dict_len, int has_dict,
    float* __restrict__ out)
{
    extern __shared__ char smem_raw[];
    uint32_t tiles = smem_u32(smem_raw);
    int tid = threadIdx.x, wid = tid >> 5, lid = tid & 31;
    int wm = wid & 1, wn = wid >> 1;          // 2 x 4 warp grid
    int nt = blockIdx.x, mt = blockIdx.y, zb = blockIdx.z;

    const __nv_bfloat16 *Ahi, *Alo, *Bhi, *Blo;
    int id = 0;
    if (MODE == 0){
        if (!lang_used(zb, lang_ids, dict_len, has_dict)) return;
        size_t ao = ((size_t)zb << 20) + (size_t)mt*128*DIM;
        Ahi = Abase_hi + ao;  Alo = Abase_lo + ao;
        Bhi = Bbase_hi + (size_t)nt*128*DIM;  Blo = Bbase_lo + (size_t)nt*128*DIM;
    } else {
        int dl = has_dict ? dict_len[0] : 32000;
        id = dl - 1 - lang_ids[zb];
        size_t ao = (size_t)zb*DIM + (size_t)mt*128*(BZ*DIM);   // rows stride BZ*DIM
        Ahi = Abase_hi + ao;  Alo = Abase_lo + ao;
        size_t bo = ((size_t)id << 20) + (size_t)nt*128*DIM;
        Bhi = Bbase_hi + bo;  Blo = Bbase_lo + bo;
    }
    const __nv_bfloat16* srcs[4] = {Ahi, Alo, Bhi, Blo};
    const size_t RSA = (MODE == 1) ? (size_t)BZ*DIM*2 : (size_t)2048;
    const size_t rstr[4] = {RSA, RSA, 2048, 2048};

    auto load_stage = [&](int kc, int st){
        uint32_t sb = tiles + st * STB;
#pragma unroll
        for (int t = 0; t < 4; t++){
            const char* g = (const char*)srcs[t] + (size_t)kc * 128;
            uint32_t d0 = sb + t * TILEB;
            size_t rs = rstr[t];
#pragma unroll
            for (int i = 0; i < 4; i++){
                int idx = tid + 256 * i;
                int row = idx >> 3, seg = idx & 7;
                cp_async16(d0 + SWZ(row*128 + seg*16), g + (size_t)row*rs + seg*16);
            }
        }
        CP_COMMIT();
    };

    float acc[4][4][4];
#pragma unroll
    for (int a = 0; a < 4; a++)
#pragma unroll
        for (int b = 0; b < 4; b++)
#pragma unroll
            for (int c = 0; c < 4; c++) acc[a][b][c] = 0.f;

    int a_row = wm*64 + (lid & 7) + ((lid >> 3) & 1) * 8;
    int a_sg  = (lid >> 4);
    int b_row = wn*32 + (lid & 7) + (lid >> 4) * 8;
    int b_sg  = (lid >> 3) & 1;

    load_stage(0, 0); load_stage(1, 1);

    for (int kc = 0; kc < NKC; kc++){
        int st = kc - (kc/3)*3;
        if (kc == NKC-1) { CP_WAIT0(); } else { CP_WAIT1(); }
        __syncthreads();
        if (kc + 2 < NKC) load_stage(kc + 2, (kc+2) - ((kc+2)/3)*3);

        uint32_t sA  = tiles + st * STB;
        uint32_t sAl = sA + TILEB, sB = sA + 2*TILEB, sBl = sA + 3*TILEB;
#pragma unroll
        for (int ks = 0; ks < 4; ks++){
            uint32_t ah[4][4], al[4][4], bh[2][4], bl[2][4];
#pragma unroll
            for (int mi = 0; mi < 4; mi++){
                uint32_t off = SWZ((a_row + mi*16)*128 + (ks*2 + a_sg)*16);
                ldsm4(ah[mi], sA  + off);
                ldsm4(al[mi], sAl + off);
            }
#pragma unroll
            for (int ni2 = 0; ni2 < 2; ni2++){
                uint32_t off = SWZ((b_row + ni2*16)*128 + (ks*2 + b_sg)*16);
                ldsm4(bh[ni2], sB  + off);
                ldsm4(bl[ni2], sBl + off);
            }
#pragma unroll
            for (int mi = 0; mi < 4; mi++)
#pragma unroll
                for (int ni = 0; ni < 4; ni++){
                    const uint32_t* bhp = &bh[ni>>1][(ni&1)*2];
                    const uint32_t* blp = &bl[ni>>1][(ni&1)*2];
                    mma16816(acc[mi][ni], ah[mi], bhp);
                    mma16816(acc[mi][ni], ah[mi], blp);
                    mma16816(acc[mi][ni], al[mi], bhp);
                }
        }
    }

    // epilogue
#pragma unroll
    for (int ni = 0; ni < 4; ni++){
        int col = nt*128 + wn*32 + ni*8 + (lid & 3)*2;
        float av0 = 0.f, av1 = 0.f;
        if (MODE == 1){
            av0 = addvec[(size_t)id*DIM + col];
            av1 = addvec[(size_t)id*DIM + col + 1];
        }
#pragma unroll
        for (int mi = 0; mi < 4; mi++){
#pragma unroll
            for (int h = 0; h < 2; h++){
                int gm = mt*128 + wm*64 + mi*16 + (lid >> 2) + h*8;
                float v0 = acc[mi][ni][h*2]   + av0;
                float v1 = acc[mi][ni][h*2+1] + av1;
                if (MODE == 0){
                    size_t o = ((size_t)zb << 20) + (size_t)gm*DIM + col;
                    __nv_bfloat16 h0 = __float2bfloat16(v0);
                    __nv_bfloat16 h1 = __float2bfloat16(v1);
                    __nv_bfloat162 hv; hv.x = h0; hv.y = h1;
                    __nv_bfloat162 lv;
                    lv.x = __float2bfloat16(v0 - __bfloat162float(h0));
                    lv.y = __float2bfloat16(v1 - __bfloat162float(h1));
                    *reinterpret_cast<__nv_bfloat162*>(&g_Bchi[o]) = hv;
                    *reinterpret_cast<__nv_bfloat162*>(&g_Bclo[o]) = lv;
                } else {
                    size_t o = ((size_t)gm*BZ + zb)*DIM + col;
                    float2 f2; f2.x = v0; f2.y = v1;
                    *reinterpret_cast<float2*>(&out[o]) = f2;
                }
            }
        }
    }
}

extern "C" void kernel_launch(void* const* d_in, const int* in_sizes, int n_in,
                              void* d_out, int out_size) {
    const float* x      = (const float*)d_in[0];
    const int*   lids   = (const int*)d_in[1];
    const float* W_base = (const float*)d_in[2];
    const float* b_base = (const float*)d_in[3];
    const float* W      = (const float*)d_in[4];
    const float* bias   = (const float*)d_in[5];
    const int*   dlen   = (n_in > 6) ? (const int*)d_in[6] : nullptr;
    int has_dict = (n_in > 6) ? 1 : 0;
    float* out = (float*)d_out;

    cudaFuncSetAttribute(gemm_kernel<0>, cudaFuncAttributeMaxDynamicSharedMemorySize, SMEM_DYN);
    cudaFuncSetAttribute(gemm_kernel<1>, cudaFuncAttributeMaxDynamicSharedMemorySize, SMEM_DYN);

    __nv_bfloat16 *Xhi, *Xlo, *Wthi, *Wtlo, *Wbthi, *Wbtlo, *Bchi, *Bclo;
    float* bc;
    cudaGetSymbolAddress((void**)&Xhi,   g_Xhi);
    cudaGetSymbolAddress((void**)&Xlo,   g_Xlo);
    cudaGetSymbolAddress((void**)&Wthi,  g_Wthi);
    cudaGetSymbolAddress((void**)&Wtlo,  g_Wtlo);
    cudaGetSymbolAddress((void**)&Wbthi, g_Wbthi);
    cudaGetSymbolAddress((void**)&Wbtlo, g_Wbtlo);
    cudaGetSymbolAddress((void**)&Bchi,  g_Bchi);
    cudaGetSymbolAddress((void**)&Bclo,  g_Bclo);
    cudaGetSymbolAddress((void**)&bc,    g_bc);

    split_x_kernel<<<(size_t)MROWS*DIM/4/256, 256>>>(x);
    {
        dim3 g(32, 32, 16), b(32, 8);
        transpose_split_kernel<<<g, b>>>(W, Wthi, Wtlo, lids, dlen, has_dict, 1);
    }
    {
        dim3 g(32, 32, 1), b(32, 8);
        transpose_split_kernel<<<g, b>>>(W_base, Wbthi, Wbtlo, lids, dlen, has_dict, 0);
    }
    bc_kernel<<<dim3(16, 8), 1024>>>(W, b_base, bias, lids, dlen, has_dict);

    // Precompute: Bt[l][e'][d] = sum_e Wt[l][e'][e] * Wbt[d][e]  (used languages only)
    {
        dim3 g(8, 8, 16), b(256);
        gemm_kernel<0><<<g, b, SMEM_DYN>>>(Wthi, Wtlo, Wbthi, Wbtlo, nullptr,
                                           lids, dlen, has_dict, nullptr);
    }
    // Main: out[s][bb][e'] = sum_d x[s][bb][d] * Bt[id][e'][d] + bc[id][e']
    {
        dim3 g(8, 16, 16), b(256);
        gemm_kernel<1><<<g, b, SMEM_DYN>>>(Xhi, Xlo, Bchi, Bclo, bc,
                                           lids, dlen, has_dict, out);
    }
}

// round 6
// speedup vs baseline: 1.5164x; 1.0145x over previous
#include <cuda_runtime.h>
#include <cuda_bf16.h>
#include <cstdint>
#include <cstddef>

#define SEQ 2048
#define BZ 16
#define DIM 1024
#define MROWS (SEQ*BZ)
#define KC 32
#define NKC 32
#define TILEA 8192            // 128 rows x 32 cols bf16
#define STB (4*TILEA)         // Ahi, Alo, Bhi, Blo
#define SMEM_DYN (3*STB)      // 96 KB

__device__ __align__(256) __nv_bfloat16 g_Xhi[(size_t)MROWS*DIM];
__device__ __align__(256) __nv_bfloat16 g_Xlo[(size_t)MROWS*DIM];
__device__ __align__(256) __nv_bfloat16 g_Wthi[(size_t)16*DIM*DIM];   // W[l]^T : [l][e'][e]
__device__ __align__(256) __nv_bfloat16 g_Wtlo[(size_t)16*DIM*DIM];
__device__ __align__(256) __nv_bfloat16 g_Wbthi[(size_t)DIM*DIM];     // W_base^T : [d][e]
__device__ __align__(256) __nv_bfloat16 g_Wbtlo[(size_t)DIM*DIM];
__device__ __align__(256) __nv_bfloat16 g_Bchi[(size_t)16*DIM*DIM];   // Bt[l][e'][d]
__device__ __align__(256) __nv_bfloat16 g_Bclo[(size_t)16*DIM*DIM];
__device__ __align__(256) float g_bc[16*DIM];

__device__ __forceinline__ uint32_t smem_u32(const void* p){
    uint32_t a;
    asm("{ .reg .u64 t; cvta.to.shared.u64 t, %1; cvt.u32.u64 %0, t; }" : "=r"(a) : "l"(p));
    return a;
}
#define SWZ64(o) ((o) ^ (((o) >> 3) & 0x30))

__device__ __forceinline__ void cp_async16(uint32_t s, const void* g){
    asm volatile("cp.async.cg.shared.global [%0], [%1], 16;" :: "r"(s), "l"(g));
}
#define CP_COMMIT() asm volatile("cp.async.commit_group;" ::: "memory")
#define CP_WAIT1()  asm volatile("cp.async.wait_group 1;" ::: "memory")
#define CP_WAIT0()  asm volatile("cp.async.wait_group 0;" ::: "memory")

__device__ __forceinline__ void ldsm4(uint32_t* r, uint32_t addr){
    asm volatile("ldmatrix.sync.aligned.m8n8.x4.shared.b16 {%0,%1,%2,%3}, [%4];"
        : "=r"(r[0]), "=r"(r[1]), "=r"(r[2]), "=r"(r[3]) : "r"(addr));
}
__device__ __forceinline__ void mma16816(float* d, const uint32_t* a, const uint32_t* b){
    asm volatile("mma.sync.aligned.m16n8k16.row.col.f32.bf16.bf16.f32 "
        "{%0,%1,%2,%3}, {%4,%5,%6,%7}, {%8,%9}, {%0,%1,%2,%3};"
        : "+f"(d[0]), "+f"(d[1]), "+f"(d[2]), "+f"(d[3])
        : "r"(a[0]), "r"(a[1]), "r"(a[2]), "r"(a[3]), "r"(b[0]), "r"(b[1]));
}

__device__ __forceinline__ bool lang_used(int l, const int* lang_ids, const int* dict_len, int has_dict){
    int dl = has_dict ? dict_len[0] : 32000;
    bool u = false;
#pragma unroll
    for (int i = 0; i < BZ; i++) u |= ((dl - 1 - lang_ids[i]) == l);
    return u;
}

// ---------------- prologue kernels ----------------
__device__ __forceinline__ void split_pack4(float4 v, uint2& ph, uint2& pl){
    float f[4] = {v.x, v.y, v.z, v.w};
    uint32_t h[4], l[4];
#pragma unroll
    for (int k = 0; k < 4; k++){
        __nv_bfloat16 hb = __float2bfloat16(f[k]);
        __nv_bfloat16 lb = __float2bfloat16(f[k] - __bfloat162float(hb));
        h[k] = (uint32_t)__bfloat16_as_ushort(hb);
        l[k] = (uint32_t)__bfloat16_as_ushort(lb);
    }
    ph.x = h[0] | (h[1] << 16); ph.y = h[2] | (h[3] << 16);
    pl.x = l[0] | (l[1] << 16); pl.y = l[2] | (l[3] << 16);
}
__global__ void split_x_kernel(const float* __restrict__ in){
    size_t i = (size_t)blockIdx.x * 256 + threadIdx.x;
    float4 v = reinterpret_cast<const float4*>(in)[i];
    uint2 ph, pl; split_pack4(v, ph, pl);
    reinterpret_cast<uint2*>(g_Xhi)[i] = ph;
    reinterpret_cast<uint2*>(g_Xlo)[i] = pl;
}
__global__ void transpose_split_kernel(const float* __restrict__ src0,
                                       __nv_bfloat16* __restrict__ dhi,
                                       __nv_bfloat16* __restrict__ dlo,
                                       const int* __restrict__ lang_ids,
                                       const int* __restrict__ dict_len,
                                       int has_dict, int check){
    int l = blockIdx.z;
    if (check && !lang_used(l, lang_ids, dict_len, has_dict)) return;
    __shared__ float t[32][33];
    int r0 = blockIdx.x * 32;
    int c0 = blockIdx.y * 32;
    int tx = threadIdx.x, ty = threadIdx.y;
    const float* src = src0 + ((size_t)l << 20);
#pragma unroll
    for (int j = 0; j < 32; j += 8)
        t[ty + j][tx] = src[(size_t)(r0 + ty + j) * DIM + c0 + tx];
    __syncthreads();
#pragma unroll
    for (int j = 0; j < 32; j += 8){
        float v = t[tx][ty + j];
        size_t o = ((size_t)l << 20) + (size_t)(c0 + ty + j) * DIM + r0 + tx;
        __nv_bfloat16 hb = __float2bfloat16(v);
        dhi[o] = hb;
        dlo[o] = __float2bfloat16(v - __bfloat162float(hb));
    }
}
__global__ void __launch_bounds__(1024,1) bc_kernel(
    const float* __restrict__ W, const float* __restrict__ b_base,
    const float* __restrict__ bias,
    const int* __restrict__ lang_ids, const int* __restrict__ dict_len, int has_dict){
    int l = blockIdx.x;
    if (!lang_used(l, lang_ids, dict_len, has_dict)) return;
    __shared__ float red[1024];
    int t  = threadIdx.x & 127;
    int es = threadIdx.x >> 7;
    int e2 = blockIdx.y * 128 + t;
    const float* Wl = W + ((size_t)l << 20);
    float s = 0.f;
#pragma unroll 4
    for (int e = es*128; e < es*128 + 128; e++)
        s += b_base[e] * Wl[(size_t)e * DIM + e2];
    red[threadIdx.x] = s;
    __syncthreads();
#pragma unroll
    for (int st = 512; st >= 128; st >>= 1){
        if (threadIdx.x < st) red[threadIdx.x] += red[threadIdx.x + st];
        __syncthreads();
    }
    if (threadIdx.x < 128)
        g_bc[l * DIM + e2] = red[threadIdx.x] + bias[(size_t)l * DIM + e2];
}

// ---------------- GEMM via mma.sync (bf16 hi/lo 3-pass), 128 threads, 2 CTA/SM ----------------
// CTA tile 128x128, warp tile 64x64 (2x2 warps), K-chunk 32, SW64 swizzle, 3 stages.
// MODE 0: Bt[l] = Wt[l] @ Wbt^T  -> g_Bchi/lo (skips unused l)
// MODE 1: out[s][bb][e'] = x[:,bb,:] @ Bt[id]^T + bc[id]
template<int MODE>
__global__ void __launch_bounds__(128,2) gemm_kernel(
    const __nv_bfloat16* __restrict__ Abase_hi, const __nv_bfloat16* __restrict__ Abase_lo,
    const __nv_bfloat16* __restrict__ Bbase_hi, const __nv_bfloat16* __restrict__ Bbase_lo,
    const float* __restrict__ addvec,
    const int* __restrict__ lang_ids, const int* __restrict__ dict_len, int has_dict,
    float* __restrict__ out)
{
    extern __shared__ char smem_raw[];
    uint32_t tiles = smem_u32(smem_raw);
    int tid = threadIdx.x, wid = tid >> 5, lid = tid & 31;
    int wm = wid & 1, wn = wid >> 1;          // 2 x 2 warp grid
    int nt = blockIdx.x, mt = blockIdx.y, zb = blockIdx.z;

    const __nv_bfloat16 *Ahi, *Alo, *Bhi, *Blo;
    int id = 0;
    if (MODE == 0){
        if (!lang_used(zb, lang_ids, dict_len, has_dict)) return;
        size_t ao = ((size_t)zb << 20) + (size_t)mt*128*DIM;
        Ahi = Abase_hi + ao;  Alo = Abase_lo + ao;
        Bhi = Bbase_hi + (size_t)nt*128*DIM;  Blo = Bbase_lo + (size_t)nt*128*DIM;
    } else {
        int dl = has_dict ? dict_len[0] : 32000;
        id = dl - 1 - lang_ids[zb];
        size_t ao = (size_t)zb*DIM + (size_t)mt*128*(BZ*DIM);   // rows stride BZ*DIM
        Ahi = Abase_hi + ao;  Alo = Abase_lo + ao;
        size_t bo = ((size_t)id << 20) + (size_t)nt*128*DIM;
        Bhi = Bbase_hi + bo;  Blo = Bbase_lo + bo;
    }
    const __nv_bfloat16* srcs[4] = {Ahi, Alo, Bhi, Blo};
    const size_t RSA = (MODE == 1) ? (size_t)BZ*DIM*2 : (size_t)2048;
    const size_t rstr[4] = {RSA, RSA, 2048, 2048};

    auto load_stage = [&](int kc, int st){
        uint32_t sb = tiles + st * STB;
#pragma unroll
        for (int t = 0; t < 4; t++){
            const char* g = (const char*)srcs[t] + (size_t)kc * (KC*2);
            uint32_t d0 = sb + t * TILEA;
            size_t rs = rstr[t];
#pragma unroll
            for (int i = 0; i < 4; i++){
                int idx = tid + 128 * i;        // 512 x 16B segments per tile
                int row = idx >> 2, seg = idx & 3;
                cp_async16(d0 + SWZ64(row*64 + seg*16), g + (size_t)row*rs + seg*16);
            }
        }
        CP_COMMIT();
    };

    float acc[4][8][4];
#pragma unroll
    for (int a = 0; a < 4; a++)
#pragma unroll
        for (int b = 0; b < 8; b++)
#pragma unroll
            for (int c = 0; c < 4; c++) acc[a][b][c] = 0.f;

    int a_row = wm*64 + (lid & 7) + ((lid >> 3) & 1) * 8;   // + mi*16
    int a_sg  = (lid >> 4);                                  // + ks*2
    int b_row = wn*64 + (lid & 7) + (lid >> 4) * 8;          // + ni2*16
    int b_sg  = (lid >> 3) & 1;                              // + ks*2

    load_stage(0, 0); load_stage(1, 1);

    for (int kc = 0; kc < NKC; kc++){
        int st = kc % 3;
        if (kc == NKC-1) { CP_WAIT0(); } else { CP_WAIT1(); }
        __syncthreads();
        if (kc + 2 < NKC) load_stage(kc + 2, (kc + 2) % 3);

        uint32_t sA  = tiles + st * STB;
        uint32_t sAl = sA + TILEA, sB = sA + 2*TILEA, sBl = sA + 3*TILEA;
#pragma unroll
        for (int ks = 0; ks < 2; ks++){
            uint32_t ah[4][4], al[4][4], bh[4][4], bl[4][4];
#pragma unroll
            for (int mi = 0; mi < 4; mi++){
                uint32_t off = SWZ64((a_row + mi*16)*64 + (ks*2 + a_sg)*16);
                ldsm4(ah[mi], sA  + off);
                ldsm4(al[mi], sAl + off);
            }
#pragma unroll
            for (int ni2 = 0; ni2 < 4; ni2++){
                uint32_t off = SWZ64((b_row + ni2*16)*64 + (ks*2 + b_sg)*16);
                ldsm4(bh[ni2], sB  + off);
                ldsm4(bl[ni2], sBl + off);
            }
#pragma unroll
            for (int mi = 0; mi < 4; mi++)
#pragma unroll
                for (int ni = 0; ni < 8; ni++){
                    const uint32_t* bhp = &bh[ni>>1][(ni&1)*2];
                    const uint32_t* blp = &bl[ni>>1][(ni&1)*2];
                    mma16816(acc[mi][ni], ah[mi], bhp);
                    mma16816(acc[mi][ni], ah[mi], blp);
                    mma16816(acc[mi][ni], al[mi], bhp);
                }
        }
    }

    // epilogue
#pragma unroll
    for (int ni = 0; ni < 8; ni++){
        int col = nt*128 + wn*64 + ni*8 + (lid & 3)*2;
        float av0 = 0.f, av1 = 0.f;
        if (MODE == 1){
            av0 = addvec[(size_t)id*DIM + col];
            av1 = addvec[(size_t)id*DIM + col + 1];
        }
#pragma unroll
        for (int mi = 0; mi < 4; mi++){
#pragma unroll
            for (int h = 0; h < 2; h++){
                int gm = mt*128 + wm*64 + mi*16 + (lid >> 2) + h*8;
                float v0 = acc[mi][ni][h*2]   + av0;
                float v1 = acc[mi][ni][h*2+1] + av1;
                if (MODE == 0){
                    size_t o = ((size_t)zb << 20) + (size_t)gm*DIM + col;
                    __nv_bfloat16 h0 = __float2bfloat16(v0);
                    __nv_bfloat16 h1 = __float2bfloat16(v1);
                    __nv_bfloat162 hv; hv.x = h0; hv.y = h1;
                    __nv_bfloat162 lv;
                    lv.x = __float2bfloat16(v0 - __bfloat162float(h0));
                    lv.y = __float2bfloat16(v1 - __bfloat162float(h1));
                    *reinterpret_cast<__nv_bfloat162*>(&g_Bchi[o]) = hv;
                    *reinterpret_cast<__nv_bfloat162*>(&g_Bclo[o]) = lv;
                } else {
                    size_t o = ((size_t)gm*BZ + zb)*DIM + col;
                    float2 f2; f2.x = v0; f2.y = v1;
                    *reinterpret_cast<float2*>(&out[o]) = f2;
                }
            }
        }
    }
}

extern "C" void kernel_launch(void* const* d_in, const int* in_sizes, int n_in,
                              void* d_out, int out_size) {
    const float* x      = (const float*)d_in[0];
    const int*   lids   = (const int*)d_in[1];
    const float* W_base = (const float*)d_in[2];
    const float* b_base = (const float*)d_in[3];
    const float* W      = (const float*)d_in[4];
    const float* bias   = (const float*)d_in[5];
    const int*   dlen   = (n_in > 6) ? (const int*)d_in[6] : nullptr;
    int has_dict = (n_in > 6) ? 1 : 0;
    float* out = (float*)d_out;

    cudaFuncSetAttribute(gemm_kernel<0>, cudaFuncAttributeMaxDynamicSharedMemorySize, SMEM_DYN);
    cudaFuncSetAttribute(gemm_kernel<1>, cudaFuncAttributeMaxDynamicSharedMemorySize, SMEM_DYN);

    __nv_bfloat16 *Xhi, *Xlo, *Wthi, *Wtlo, *Wbthi, *Wbtlo, *Bchi, *Bclo;
    float* bc;
    cudaGetSymbolAddress((void**)&Xhi,   g_Xhi);
    cudaGetSymbolAddress((void**)&Xlo,   g_Xlo);
    cudaGetSymbolAddress((void**)&Wthi,  g_Wthi);
    cudaGetSymbolAddress((void**)&Wtlo,  g_Wtlo);
    cudaGetSymbolAddress((void**)&Wbthi, g_Wbthi);
    cudaGetSymbolAddress((void**)&Wbtlo, g_Wbtlo);
    cudaGetSymbolAddress((void**)&Bchi,  g_Bchi);
    cudaGetSymbolAddress((void**)&Bclo,  g_Bclo);
    cudaGetSymbolAddress((void**)&bc,    g_bc);

    split_x_kernel<<<(size_t)MROWS*DIM/4/256, 256>>>(x);
    {
        dim3 g(32, 32, 16), b(32, 8);
        transpose_split_kernel<<<g, b>>>(W, Wthi, Wtlo, lids, dlen, has_dict, 1);
    }
    {
        dim3 g(32, 32, 1), b(32, 8);
        transpose_split_kernel<<<g, b>>>(W_base, Wbthi, Wbtlo, lids, dlen, has_dict, 0);
    }
    bc_kernel<<<dim3(16, 8), 1024>>>(W, b_base, bias, lids, dlen, has_dict);

    // Precompute: Bt[l][e'][d] = sum_e Wt[l][e'][e] * Wbt[d][e]  (used languages only)
    {
        dim3 g(8, 8, 16), b(128);
        gemm_kernel<0><<<g, b, SMEM_DYN>>>(Wthi, Wtlo, Wbthi, Wbtlo, nullptr,
                                           lids, dlen, has_dict, nullptr);
    }
    // Main: out[s][bb][e'] = sum_d x[s][bb][d] * Bt[id][e'][d] + bc[id][e']
    {
        dim3 g(8, 16, 16), b(128);
        gemm_kernel<1><<<g, b, SMEM_DYN>>>(Xhi, Xlo, Bchi, Bclo, bc,
                                           lids, dlen, has_dict, out);
    }
}

// round 7
// speedup vs baseline: 1.9496x; 1.2857x over previous
#include <cuda_runtime.h>
#include <cuda_fp16.h>
#include <cstdint>
#include <cstddef>

#define SEQ 2048
#define BZ 16
#define DIM 1024
#define MROWS (SEQ*BZ)
#define KC 32
#define NKC 32
#define TILEA 8192            // 128 rows x 32 cols fp16

__device__ __align__(256) __half g_Xh[(size_t)MROWS*DIM];           // fp16(x)
__device__ __align__(256) __half g_Wthi[(size_t)16*DIM*DIM];        // W[l]^T hi : [l][e'][e]
__device__ __align__(256) __half g_Wtlo[(size_t)16*DIM*DIM];
__device__ __align__(256) __half g_Wbthi[(size_t)DIM*DIM];          // W_base^T hi : [d][e]
__device__ __align__(256) __half g_Wbtlo[(size_t)DIM*DIM];
__device__ __align__(256) __half g_Bchi[(size_t)16*DIM*DIM];        // Bt[l][e'][d] hi
__device__ __align__(256) __half g_Bclo[(size_t)16*DIM*DIM];
__device__ __align__(256) float g_bc[16*DIM];

__device__ __forceinline__ uint32_t smem_u32(const void* p){
    uint32_t a;
    asm("{ .reg .u64 t; cvta.to.shared.u64 t, %1; cvt.u32.u64 %0, t; }" : "=r"(a) : "l"(p));
    return a;
}
#define SWZ64(o) ((o) ^ (((o) >> 3) & 0x30))

__device__ __forceinline__ void cp_async16(uint32_t s, const void* g){
    asm volatile("cp.async.cg.shared.global [%0], [%1], 16;" :: "r"(s), "l"(g));
}
#define CP_COMMIT() asm volatile("cp.async.commit_group;" ::: "memory")
#define CP_WAIT1()  asm volatile("cp.async.wait_group 1;" ::: "memory")
#define CP_WAIT0()  asm volatile("cp.async.wait_group 0;" ::: "memory")

__device__ __forceinline__ void ldsm4(uint32_t* r, uint32_t addr){
    asm volatile("ldmatrix.sync.aligned.m8n8.x4.shared.b16 {%0,%1,%2,%3}, [%4];"
        : "=r"(r[0]), "=r"(r[1]), "=r"(r[2]), "=r"(r[3]) : "r"(addr));
}
__device__ __forceinline__ void mma16816h(float* d, const uint32_t* a, const uint32_t* b){
    asm volatile("mma.sync.aligned.m16n8k16.row.col.f32.f16.f16.f32 "
        "{%0,%1,%2,%3}, {%4,%5,%6,%7}, {%8,%9}, {%0,%1,%2,%3};"
        : "+f"(d[0]), "+f"(d[1]), "+f"(d[2]), "+f"(d[3])
        : "r"(a[0]), "r"(a[1]), "r"(a[2]), "r"(a[3]), "r"(b[0]), "r"(b[1]));
}

__device__ __forceinline__ bool lang_used(int l, const int* lang_ids, const int* dict_len, int has_dict){
    int dl = has_dict ? dict_len[0] : 32000;
    bool u = false;
#pragma unroll
    for (int i = 0; i < BZ; i++) u |= ((dl - 1 - lang_ids[i]) == l);
    return u;
}

// ---------------- prologue kernels ----------------
__global__ void split_x_kernel(const float* __restrict__ in){
    size_t i = (size_t)blockIdx.x * 256 + threadIdx.x;
    float4 v = reinterpret_cast<const float4*>(in)[i];
    uint32_t h[4];
    float f[4] = {v.x, v.y, v.z, v.w};
#pragma unroll
    for (int k = 0; k < 4; k++)
        h[k] = (uint32_t)__half_as_ushort(__float2half_rn(f[k]));
    uint2 ph; ph.x = h[0] | (h[1] << 16); ph.y = h[2] | (h[3] << 16);
    reinterpret_cast<uint2*>(g_Xh)[i] = ph;
}
// src [z][1024][1024] fp32 -> dst [z][c][r] fp16 hi/lo (transpose within each z)
__global__ void transpose_split_kernel(const float* __restrict__ src0,
                                       __half* __restrict__ dhi,
                                       __half* __restrict__ dlo,
                                       const int* __restrict__ lang_ids,
                                       const int* __restrict__ dict_len,
                                       int has_dict, int check){
    int l = blockIdx.z;
    if (check && !lang_used(l, lang_ids, dict_len, has_dict)) return;
    __shared__ float t[32][33];
    int r0 = blockIdx.x * 32;
    int c0 = blockIdx.y * 32;
    int tx = threadIdx.x, ty = threadIdx.y;
    const float* src = src0 + ((size_t)l << 20);
#pragma unroll
    for (int j = 0; j < 32; j += 8)
        t[ty + j][tx] = src[(size_t)(r0 + ty + j) * DIM + c0 + tx];
    __syncthreads();
#pragma unroll
    for (int j = 0; j < 32; j += 8){
        float v = t[tx][ty + j];
        size_t o = ((size_t)l << 20) + (size_t)(c0 + ty + j) * DIM + r0 + tx;
        __half hb = __float2half_rn(v);
        dhi[o] = hb;
        dlo[o] = __float2half_rn(v - __half2float(hb));
    }
}
__global__ void __launch_bounds__(1024,1) bc_kernel(
    const float* __restrict__ W, const float* __restrict__ b_base,
    const float* __restrict__ bias,
    const int* __restrict__ lang_ids, const int* __restrict__ dict_len, int has_dict){
    int l = blockIdx.x;
    if (!lang_used(l, lang_ids, dict_len, has_dict)) return;
    __shared__ float red[1024];
    int t  = threadIdx.x & 127;
    int es = threadIdx.x >> 7;
    int e2 = blockIdx.y * 128 + t;
    const float* Wl = W + ((size_t)l << 20);
    float s = 0.f;
#pragma unroll 4
    for (int e = es*128; e < es*128 + 128; e++)
        s += b_base[e] * Wl[(size_t)e * DIM + e2];
    red[threadIdx.x] = s;
    __syncthreads();
#pragma unroll
    for (int st = 512; st >= 128; st >>= 1){
        if (threadIdx.x < st) red[threadIdx.x] += red[threadIdx.x + st];
        __syncthreads();
    }
    if (threadIdx.x < 128)
        g_bc[l * DIM + e2] = red[threadIdx.x] + bias[(size_t)l * DIM + e2];
}

// ---------------- GEMM via mma.sync fp16, 128 threads ----------------
// CTA tile 128x128, warp tile 64x64 (2x2), K-chunk 32, SW64, 3 stages.
// MODE 0 (precompute, 3-pass): Bt[l] = Wt[l] @ Wbt^T -> g_Bchi/lo (skips unused l)
// MODE 1 (main, 2-pass):       out[s][bb][e'] = xh[:,bb,:] @ Bt[id]^T + bc[id]
template<int MODE>
__global__ void __launch_bounds__(128,2) gemm_kernel(
    const __half* __restrict__ A0, const __half* __restrict__ A1,
    const __half* __restrict__ B0, const __half* __restrict__ B1,
    const float* __restrict__ addvec,
    const int* __restrict__ lang_ids, const int* __restrict__ dict_len, int has_dict,
    float* __restrict__ out)
{
    constexpr int NT  = (MODE == 0) ? 4 : 3;
    constexpr int STBm = NT * TILEA;
    extern __shared__ char smem_raw[];
    uint32_t tiles = smem_u32(smem_raw);
    int tid = threadIdx.x, wid = tid >> 5, lid = tid & 31;
    int wm = wid & 1, wn = wid >> 1;
    int nt = blockIdx.x, mt = blockIdx.y, zb = blockIdx.z;

    const __half* srcs[NT];
    size_t rstr[NT];
    int id = 0;
    if (MODE == 0){
        if (!lang_used(zb, lang_ids, dict_len, has_dict)) return;
        size_t ao = ((size_t)zb << 20) + (size_t)mt*128*DIM;
        size_t bo = (size_t)nt*128*DIM;
        srcs[0] = A0 + ao; srcs[1] = A1 + ao; srcs[2] = B0 + bo; srcs[3] = B1 + bo;
        rstr[0] = rstr[1] = rstr[2] = rstr[3] = 2048;
    } else {
        int dl = has_dict ? dict_len[0] : 32000;
        id = dl - 1 - lang_ids[zb];
        size_t ao = (size_t)zb*DIM + (size_t)mt*128*(BZ*DIM);
        size_t bo = ((size_t)id << 20) + (size_t)nt*128*DIM;
        srcs[0] = A0 + ao; srcs[1] = B0 + bo; srcs[2] = B1 + bo;
        rstr[0] = (size_t)BZ*DIM*2; rstr[1] = rstr[2] = 2048;
    }

    auto load_stage = [&](int kc, int st){
        uint32_t sb = tiles + st * STBm;
#pragma unroll
        for (int t = 0; t < NT; t++){
            const char* g = (const char*)srcs[t] + (size_t)kc * (KC*2);
            uint32_t d0 = sb + t * TILEA;
            size_t rs = rstr[t];
#pragma unroll
            for (int i = 0; i < 4; i++){
                int idx = tid + 128 * i;
                int row = idx >> 2, seg = idx & 3;
                cp_async16(d0 + SWZ64(row*64 + seg*16), g + (size_t)row*rs + seg*16);
            }
        }
        CP_COMMIT();
    };

    float acc[4][8][4];
#pragma unroll
    for (int a = 0; a < 4; a++)
#pragma unroll
        for (int b = 0; b < 8; b++)
#pragma unroll
            for (int c = 0; c < 4; c++) acc[a][b][c] = 0.f;

    int a_row = wm*64 + (lid & 7) + ((lid >> 3) & 1) * 8;
    int a_sg  = (lid >> 4);
    int b_row = wn*64 + (lid & 7) + (lid >> 4) * 8;
    int b_sg  = (lid >> 3) & 1;

    load_stage(0, 0); load_stage(1, 1);

    for (int kc = 0; kc < NKC; kc++){
        int st = kc % 3;
        if (kc == NKC-1) { CP_WAIT0(); } else { CP_WAIT1(); }
        __syncthreads();
        if (kc + 2 < NKC) load_stage(kc + 2, (kc + 2) % 3);

        uint32_t sb = tiles + st * STBm;
#pragma unroll
        for (int ks = 0; ks < 2; ks++){
            if (MODE == 0){
                uint32_t sA = sb, sAl = sb + TILEA, sB = sb + 2*TILEA, sBl = sb + 3*TILEA;
                uint32_t ah[4][4], al[4][4], bh[4][4], bl[4][4];
#pragma unroll
                for (int mi = 0; mi < 4; mi++){
                    uint32_t off = SWZ64((a_row + mi*16)*64 + (ks*2 + a_sg)*16);
                    ldsm4(ah[mi], sA  + off);
                    ldsm4(al[mi], sAl + off);
                }
#pragma unroll
                for (int ni2 = 0; ni2 < 4; ni2++){
                    uint32_t off = SWZ64((b_row + ni2*16)*64 + (ks*2 + b_sg)*16);
                    ldsm4(bh[ni2], sB  + off);
                    ldsm4(bl[ni2], sBl + off);
                }
#pragma unroll
                for (int mi = 0; mi < 4; mi++)
#pragma unroll
                    for (int ni = 0; ni < 8; ni++){
                        const uint32_t* bhp = &bh[ni>>1][(ni&1)*2];
                        const uint32_t* blp = &bl[ni>>1][(ni&1)*2];
                        mma16816h(acc[mi][ni], ah[mi], bhp);
                        mma16816h(acc[mi][ni], ah[mi], blp);
                        mma16816h(acc[mi][ni], al[mi], bhp);
                    }
            } else {
                uint32_t sA = sb, sB = sb + TILEA, sBl = sb + 2*TILEA;
                uint32_t ah[4][4], bh[4][4], bl[4][4];
#pragma unroll
                for (int mi = 0; mi < 4; mi++){
                    uint32_t off = SWZ64((a_row + mi*16)*64 + (ks*2 + a_sg)*16);
                    ldsm4(ah[mi], sA + off);
                }
#pragma unroll
                for (int ni2 = 0; ni2 < 4; ni2++){
                    uint32_t off = SWZ64((b_row + ni2*16)*64 + (ks*2 + b_sg)*16);
                    ldsm4(bh[ni2], sB  + off);
                    ldsm4(bl[ni2], sBl + off);
                }
#pragma unroll
                for (int mi = 0; mi < 4; mi++)
#pragma unroll
                    for (int ni = 0; ni < 8; ni++){
                        const uint32_t* bhp = &bh[ni>>1][(ni&1)*2];
                        const uint32_t* blp = &bl[ni>>1][(ni&1)*2];
                        mma16816h(acc[mi][ni], ah[mi], bhp);
                        mma16816h(acc[mi][ni], ah[mi], blp);
                    }
            }
        }
    }

    // epilogue
#pragma unroll
    for (int ni = 0; ni < 8; ni++){
        int col = nt*128 + wn*64 + ni*8 + (lid & 3)*2;
        float av0 = 0.f, av1 = 0.f;
        if (MODE == 1){
            av0 = addvec[(size_t)id*DIM + col];
            av1 = addvec[(size_t)id*DIM + col + 1];
        }
#pragma unroll
        for (int mi = 0; mi < 4; mi++){
#pragma unroll
            for (int h = 0; h < 2; h++){
                int gm = mt*128 + wm*64 + mi*16 + (lid >> 2) + h*8;
                float v0 = acc[mi][ni][h*2]   + av0;
                float v1 = acc[mi][ni][h*2+1] + av1;
                if (MODE == 0){
                    size_t o = ((size_t)zb << 20) + (size_t)gm*DIM + col;
                    __half h0 = __float2half_rn(v0);
                    __half h1 = __float2half_rn(v1);
                    uint32_t hv = (uint32_t)__half_as_ushort(h0) | ((uint32_t)__half_as_ushort(h1) << 16);
                    uint32_t lv = (uint32_t)__half_as_ushort(__float2half_rn(v0 - __half2float(h0)))
                                | ((uint32_t)__half_as_ushort(__float2half_rn(v1 - __half2float(h1))) << 16);
                    *reinterpret_cast<uint32_t*>(&g_Bchi[o]) = hv;
                    *reinterpret_cast<uint32_t*>(&g_Bclo[o]) = lv;
                } else {
                    size_t o = ((size_t)gm*BZ + zb)*DIM + col;
                    float2 f2; f2.x = v0; f2.y = v1;
                    *reinterpret_cast<float2*>(&out[o]) = f2;
                }
            }
        }
    }
}

extern "C" void kernel_launch(void* const* d_in, const int* in_sizes, int n_in,
                              void* d_out, int out_size) {
    const float* x      = (const float*)d_in[0];
    const int*   lids   = (const int*)d_in[1];
    const float* W_base = (const float*)d_in[2];
    const float* b_base = (const float*)d_in[3];
    const float* W      = (const float*)d_in[4];
    const float* bias   = (const float*)d_in[5];
    const int*   dlen   = (n_in > 6) ? (const int*)d_in[6] : nullptr;
    int has_dict = (n_in > 6) ? 1 : 0;
    float* out = (float*)d_out;

    const int SMEM0 = 3 * 4 * TILEA;   // 96 KB
    const int SMEM1 = 3 * 3 * TILEA;   // 72 KB
    cudaFuncSetAttribute(gemm_kernel<0>, cudaFuncAttributeMaxDynamicSharedMemorySize, SMEM0);
    cudaFuncSetAttribute(gemm_kernel<1>, cudaFuncAttributeMaxDynamicSharedMemorySize, SMEM1);

    __half *Xh, *Wthi, *Wtlo, *Wbthi, *Wbtlo, *Bchi, *Bclo;
    float* bc;
    cudaGetSymbolAddress((void**)&Xh,    g_Xh);
    cudaGetSymbolAddress((void**)&Wthi,  g_Wthi);
    cudaGetSymbolAddress((void**)&Wtlo,  g_Wtlo);
    cudaGetSymbolAddress((void**)&Wbthi, g_Wbthi);
    cudaGetSymbolAddress((void**)&Wbtlo, g_Wbtlo);
    cudaGetSymbolAddress((void**)&Bchi,  g_Bchi);
    cudaGetSymbolAddress((void**)&Bclo,  g_Bclo);
    cudaGetSymbolAddress((void**)&bc,    g_bc);

    split_x_kernel<<<(size_t)MROWS*DIM/4/256, 256>>>(x);
    {
        dim3 g(32, 32, 16), b(32, 8);
        transpose_split_kernel<<<g, b>>>(W, Wthi, Wtlo, lids, dlen, has_dict, 1);
    }
    {
        dim3 g(32, 32, 1), b(32, 8);
        transpose_split_kernel<<<g, b>>>(W_base, Wbthi, Wbtlo, lids, dlen, has_dict, 0);
    }
    bc_kernel<<<dim3(16, 8), 1024>>>(W, b_base, bias, lids, dlen, has_dict);

    // Precompute (3-pass fp16): Bt[l][e'][d] = sum_e Wt[l][e'][e] * Wbt[d][e]
    {
        dim3 g(8, 8, 16), b(128);
        gemm_kernel<0><<<g, b, SMEM0>>>(Wthi, Wtlo, Wbthi, Wbtlo, nullptr,
                                        lids, dlen, has_dict, nullptr);
    }
    // Main (2-pass fp16): out[s][bb][e'] = sum_d xh[s][bb][d] * Bt[id][e'][d] + bc[id][e']
    {
        dim3 g(8, 16, 16), b(128);
        gemm_kernel<1><<<g, b, SMEM1>>>(Xh, nullptr, Bchi, Bclo, bc,
                                        lids, dlen, has_dict, out);
    }
}

// round 8
// speedup vs baseline: 2.1480x; 1.1018x over previous
#include <cuda_runtime.h>
#include <cuda_fp16.h>
#include <cstdint>
#include <cstddef>

#define SEQ 2048
#define BZ 16
#define DIM 1024
#define MROWS (SEQ*BZ)
#define KC 32
#define NKC 32
#define TILEA 8192            // 128 rows x 32 cols fp16
#define SMEM_G (3*3*TILEA)    // 72 KB, both modes

__device__ __align__(256) __half g_Xh[(size_t)MROWS*DIM];           // fp16(x)
__device__ __align__(256) __half g_Wthi[(size_t)16*DIM*DIM];        // fp16(W[l]^T) : [l][e'][e]
__device__ __align__(256) __half g_Wbthi[(size_t)DIM*DIM];          // W_base^T hi : [d][e]
__device__ __align__(256) __half g_Wbtlo[(size_t)DIM*DIM];
__device__ __align__(256) __half g_Bchi[(size_t)16*DIM*DIM];        // Bt[l][e'][d] hi
__device__ __align__(256) __half g_Bclo[(size_t)16*DIM*DIM];
__device__ __align__(256) float g_bc[16*DIM];

__device__ __forceinline__ uint32_t smem_u32(const void* p){
    uint32_t a;
    asm("{ .reg .u64 t; cvta.to.shared.u64 t, %1; cvt.u32.u64 %0, t; }" : "=r"(a) : "l"(p));
    return a;
}
#define SWZ64(o) ((o) ^ (((o) >> 3) & 0x30))

__device__ __forceinline__ void cp_async16(uint32_t s, const void* g){
    asm volatile("cp.async.cg.shared.global [%0], [%1], 16;" :: "r"(s), "l"(g));
}
#define CP_COMMIT() asm volatile("cp.async.commit_group;" ::: "memory")
#define CP_WAIT1()  asm volatile("cp.async.wait_group 1;" ::: "memory")
#define CP_WAIT0()  asm volatile("cp.async.wait_group 0;" ::: "memory")

__device__ __forceinline__ void ldsm4(uint32_t* r, uint32_t addr){
    asm volatile("ldmatrix.sync.aligned.m8n8.x4.shared.b16 {%0,%1,%2,%3}, [%4];"
        : "=r"(r[0]), "=r"(r[1]), "=r"(r[2]), "=r"(r[3]) : "r"(addr));
}
__device__ __forceinline__ void mma16816h(float* d, const uint32_t* a, const uint32_t* b){
    asm volatile("mma.sync.aligned.m16n8k16.row.col.f32.f16.f16.f32 "
        "{%0,%1,%2,%3}, {%4,%5,%6,%7}, {%8,%9}, {%0,%1,%2,%3};"
        : "+f"(d[0]), "+f"(d[1]), "+f"(d[2]), "+f"(d[3])
        : "r"(a[0]), "r"(a[1]), "r"(a[2]), "r"(a[3]), "r"(b[0]), "r"(b[1]));
}

__device__ __forceinline__ bool lang_used(int l, const int* lang_ids, const int* dict_len, int has_dict){
    int dl = has_dict ? dict_len[0] : 32000;
    bool u = false;
#pragma unroll
    for (int i = 0; i < BZ; i++) u |= ((dl - 1 - lang_ids[i]) == l);
    return u;
}

// ---------------- prologue kernels ----------------
__global__ void split_x_kernel(const float* __restrict__ in){
    size_t i = (size_t)blockIdx.x * 256 + threadIdx.x;
    float4 v = reinterpret_cast<const float4*>(in)[i];
    uint32_t h[4];
    float f[4] = {v.x, v.y, v.z, v.w};
#pragma unroll
    for (int k = 0; k < 4; k++)
        h[k] = (uint32_t)__half_as_ushort(__float2half_rn(f[k]));
    uint2 ph; ph.x = h[0] | (h[1] << 16); ph.y = h[2] | (h[3] << 16);
    reinterpret_cast<uint2*>(g_Xh)[i] = ph;
}
// src [z][1024][1024] fp32 -> dst [z][c][r] fp16 (optionally hi/lo split)
__global__ void transpose_split_kernel(const float* __restrict__ src0,
                                       __half* __restrict__ dhi,
                                       __half* __restrict__ dlo,   // may be null
                                       const int* __restrict__ lang_ids,
                                       const int* __restrict__ dict_len,
                                       int has_dict, int check){
    int l = blockIdx.z;
    if (check && !lang_used(l, lang_ids, dict_len, has_dict)) return;
    __shared__ float t[32][33];
    int r0 = blockIdx.x * 32;
    int c0 = blockIdx.y * 32;
    int tx = threadIdx.x, ty = threadIdx.y;
    const float* src = src0 + ((size_t)l << 20);
#pragma unroll
    for (int j = 0; j < 32; j += 8)
        t[ty + j][tx] = src[(size_t)(r0 + ty + j) * DIM + c0 + tx];
    __syncthreads();
#pragma unroll
    for (int j = 0; j < 32; j += 8){
        float v = t[tx][ty + j];
        size_t o = ((size_t)l << 20) + (size_t)(c0 + ty + j) * DIM + r0 + tx;
        __half hb = __float2half_rn(v);
        dhi[o] = hb;
        if (dlo) dlo[o] = __float2half_rn(v - __half2float(hb));
    }
}
__global__ void __launch_bounds__(1024,1) bc_kernel(
    const float* __restrict__ W, const float* __restrict__ b_base,
    const float* __restrict__ bias,
    const int* __restrict__ lang_ids, const int* __restrict__ dict_len, int has_dict){
    int l = blockIdx.x;
    if (!lang_used(l, lang_ids, dict_len, has_dict)) return;
    __shared__ float red[1024];
    int t  = threadIdx.x & 127;
    int es = threadIdx.x >> 7;
    int e2 = blockIdx.y * 128 + t;
    const float* Wl = W + ((size_t)l << 20);
    float s = 0.f;
#pragma unroll 8
    for (int e = es*128; e < es*128 + 128; e++)
        s += b_base[e] * Wl[(size_t)e * DIM + e2];
    red[threadIdx.x] = s;
    __syncthreads();
#pragma unroll
    for (int st = 512; st >= 128; st >>= 1){
        if (threadIdx.x < st) red[threadIdx.x] += red[threadIdx.x + st];
        __syncthreads();
    }
    if (threadIdx.x < 128)
        g_bc[l * DIM + e2] = red[threadIdx.x] + bias[(size_t)l * DIM + e2];
}

// ---------------- GEMM via mma.sync fp16 (A 1-pass, B hi/lo 2-pass) ----------------
// CTA tile 128x128, warp tile 64x64 (2x2), K-chunk 32, SW64, 3 stages, 128 threads.
// MODE 0: Bt[l] = Wt[l] @ (Wbt_hi + Wbt_lo)^T -> split-store g_Bchi/lo (skips unused l)
// MODE 1: out[s][bb][e'] = xh[:,bb,:] @ (Bt_hi + Bt_lo)[id]^T + bc[id]
template<int MODE>
__global__ void __launch_bounds__(128,2) gemm_kernel(
    const __half* __restrict__ A0,
    const __half* __restrict__ B0, const __half* __restrict__ B1,
    const float* __restrict__ addvec,
    const int* __restrict__ lang_ids, const int* __restrict__ dict_len, int has_dict,
    float* __restrict__ out)
{
    extern __shared__ char smem_raw[];
    uint32_t tiles = smem_u32(smem_raw);
    int tid = threadIdx.x, wid = tid >> 5, lid = tid & 31;
    int wm = wid & 1, wn = wid >> 1;
    int nt = blockIdx.x, mt = blockIdx.y, zb = blockIdx.z;

    const __half* srcs[3];
    size_t rstr[3];
    int id = 0;
    if (MODE == 0){
        if (!lang_used(zb, lang_ids, dict_len, has_dict)) return;
        size_t ao = ((size_t)zb << 20) + (size_t)mt*128*DIM;
        size_t bo = (size_t)nt*128*DIM;
        srcs[0] = A0 + ao; srcs[1] = B0 + bo; srcs[2] = B1 + bo;
        rstr[0] = rstr[1] = rstr[2] = 2048;
    } else {
        int dl = has_dict ? dict_len[0] : 32000;
        id = dl - 1 - lang_ids[zb];
        size_t ao = (size_t)zb*DIM + (size_t)mt*128*(BZ*DIM);
        size_t bo = ((size_t)id << 20) + (size_t)nt*128*DIM;
        srcs[0] = A0 + ao; srcs[1] = B0 + bo; srcs[2] = B1 + bo;
        rstr[0] = (size_t)BZ*DIM*2; rstr[1] = rstr[2] = 2048;
    }

    auto load_stage = [&](int kc, int st){
        uint32_t sb = tiles + st * (3*TILEA);
#pragma unroll
        for (int t = 0; t < 3; t++){
            const char* g = (const char*)srcs[t] + (size_t)kc * (KC*2);
            uint32_t d0 = sb + t * TILEA;
            size_t rs = rstr[t];
#pragma unroll
            for (int i = 0; i < 4; i++){
                int idx = tid + 128 * i;
                int row = idx >> 2, seg = idx & 3;
                cp_async16(d0 + SWZ64(row*64 + seg*16), g + (size_t)row*rs + seg*16);
            }
        }
        CP_COMMIT();
    };

    float acc[4][8][4];
#pragma unroll
    for (int a = 0; a < 4; a++)
#pragma unroll
        for (int b = 0; b < 8; b++)
#pragma unroll
            for (int c = 0; c < 4; c++) acc[a][b][c] = 0.f;

    int a_row = wm*64 + (lid & 7) + ((lid >> 3) & 1) * 8;
    int a_sg  = (lid >> 4);
    int b_row = wn*64 + (lid & 7) + (lid >> 4) * 8;
    int b_sg  = (lid >> 3) & 1;

    load_stage(0, 0); load_stage(1, 1);

    for (int kc = 0; kc < NKC; kc++){
        int st = kc % 3;
        if (kc == NKC-1) { CP_WAIT0(); } else { CP_WAIT1(); }
        __syncthreads();
        if (kc + 2 < NKC) load_stage(kc + 2, (kc + 2) % 3);

        uint32_t sb = tiles + st * (3*TILEA);
        uint32_t sA = sb, sB = sb + TILEA, sBl = sb + 2*TILEA;
#pragma unroll
        for (int ks = 0; ks < 2; ks++){
            uint32_t ah[4][4], bh[4][4], bl[4][4];
#pragma unroll
            for (int mi = 0; mi < 4; mi++){
                uint32_t off = SWZ64((a_row + mi*16)*64 + (ks*2 + a_sg)*16);
                ldsm4(ah[mi], sA + off);
            }
#pragma unroll
            for (int ni2 = 0; ni2 < 4; ni2++){
                uint32_t off = SWZ64((b_row + ni2*16)*64 + (ks*2 + b_sg)*16);
                ldsm4(bh[ni2], sB  + off);
                ldsm4(bl[ni2], sBl + off);
            }
#pragma unroll
            for (int mi = 0; mi < 4; mi++)
#pragma unroll
                for (int ni = 0; ni < 8; ni++){
                    const uint32_t* bhp = &bh[ni>>1][(ni&1)*2];
                    const uint32_t* blp = &bl[ni>>1][(ni&1)*2];
                    mma16816h(acc[mi][ni], ah[mi], bhp);
                    mma16816h(acc[mi][ni], ah[mi], blp);
                }
        }
    }

    // epilogue
#pragma unroll
    for (int ni = 0; ni < 8; ni++){
        int col = nt*128 + wn*64 + ni*8 + (lid & 3)*2;
        float av0 = 0.f, av1 = 0.f;
        if (MODE == 1){
            av0 = addvec[(size_t)id*DIM + col];
            av1 = addvec[(size_t)id*DIM + col + 1];
        }
#pragma unroll
        for (int mi = 0; mi < 4; mi++){
#pragma unroll
            for (int h = 0; h < 2; h++){
                int gm = mt*128 + wm*64 + mi*16 + (lid >> 2) + h*8;
                float v0 = acc[mi][ni][h*2]   + av0;
                float v1 = acc[mi][ni][h*2+1] + av1;
                if (MODE == 0){
                    size_t o = ((size_t)zb << 20) + (size_t)gm*DIM + col;
                    __half h0 = __float2half_rn(v0);
                    __half h1 = __float2half_rn(v1);
                    uint32_t hv = (uint32_t)__half_as_ushort(h0) | ((uint32_t)__half_as_ushort(h1) << 16);
                    uint32_t lv = (uint32_t)__half_as_ushort(__float2half_rn(v0 - __half2float(h0)))
                                | ((uint32_t)__half_as_ushort(__float2half_rn(v1 - __half2float(h1))) << 16);
                    *reinterpret_cast<uint32_t*>(&g_Bchi[o]) = hv;
                    *reinterpret_cast<uint32_t*>(&g_Bclo[o]) = lv;
                } else {
                    size_t o = ((size_t)gm*BZ + zb)*DIM + col;
                    float2 f2; f2.x = v0; f2.y = v1;
                    *reinterpret_cast<float2*>(&out[o]) = f2;
                }
            }
        }
    }
}

extern "C" void kernel_launch(void* const* d_in, const int* in_sizes, int n_in,
                              void* d_out, int out_size) {
    const float* x      = (const float*)d_in[0];
    const int*   lids   = (const int*)d_in[1];
    const float* W_base = (const float*)d_in[2];
    const float* b_base = (const float*)d_in[3];
    const float* W      = (const float*)d_in[4];
    const float* bias   = (const float*)d_in[5];
    const int*   dlen   = (n_in > 6) ? (const int*)d_in[6] : nullptr;
    int has_dict = (n_in > 6) ? 1 : 0;
    float* out = (float*)d_out;

    cudaFuncSetAttribute(gemm_kernel<0>, cudaFuncAttributeMaxDynamicSharedMemorySize, SMEM_G);
    cudaFuncSetAttribute(gemm_kernel<1>, cudaFuncAttributeMaxDynamicSharedMemorySize, SMEM_G);

    __half *Xh, *Wthi, *Wbthi, *Wbtlo, *Bchi, *Bclo;
    float* bc;
    cudaGetSymbolAddress((void**)&Xh,    g_Xh);
    cudaGetSymbolAddress((void**)&Wthi,  g_Wthi);
    cudaGetSymbolAddress((void**)&Wbthi, g_Wbthi);
    cudaGetSymbolAddress((void**)&Wbtlo, g_Wbtlo);
    cudaGetSymbolAddress((void**)&Bchi,  g_Bchi);
    cudaGetSymbolAddress((void**)&Bclo,  g_Bclo);
    cudaGetSymbolAddress((void**)&bc,    g_bc);

    split_x_kernel<<<(size_t)MROWS*DIM/4/256, 256>>>(x);
    {
        dim3 g(32, 32, 16), b(32, 8);
        transpose_split_kernel<<<g, b>>>(W, Wthi, nullptr, lids, dlen, has_dict, 1);
    }
    {
        dim3 g(32, 32, 1), b(32, 8);
        transpose_split_kernel<<<g, b>>>(W_base, Wbthi, Wbtlo, lids, dlen, has_dict, 0);
    }
    bc_kernel<<<dim3(16, 8), 1024>>>(W, b_base, bias, lids, dlen, has_dict);

    // Precompute (2-pass): Bt[l][e'][d] = sum_e Wt[l][e'][e] * (Wbt_hi+Wbt_lo)[d][e]
    {
        dim3 g(8, 8, 16), b(128);
        gemm_kernel<0><<<g, b, SMEM_G>>>(Wthi, Wbthi, Wbtlo, nullptr,
                                         lids, dlen, has_dict, nullptr);
    }
    // Main (2-pass): out[s][bb][e'] = sum_d xh[s][bb][d] * (Bt_hi+Bt_lo)[id][e'][d] + bc[id][e']
    {
        dim3 g(8, 16, 16), b(128);
        gemm_kernel<1><<<g, b, SMEM_G>>>(Xh, Bchi, Bclo, bc,
                                         lids, dlen, has_dict, out);
    }
}

// round 9
// speedup vs baseline: 3.7779x; 1.7588x over previous
#include <cuda_runtime.h>
#include <cuda_fp16.h>
#include <cstdint>
#include <cstddef>

#define SEQ 2048
#define BZ 16
#define DIM 1024
#define MROWS (SEQ*BZ)
#define KC 32
#define NKC 32
#define TILEA 8192            // 128 rows x 32 cols fp16
#define SMEM_G (3*2*TILEA)    // 48 KB, both modes

__device__ __align__(256) __half g_Xh[(size_t)MROWS*DIM];           // fp16(x)
__device__ __align__(256) __half g_Wt[(size_t)16*DIM*DIM];          // fp16(W[l]^T) : [l][e'][e]
__device__ __align__(256) __half g_Wbt[(size_t)DIM*DIM];            // fp16(W_base^T) : [d][e]
__device__ __align__(256) __half g_Bc[(size_t)16*DIM*DIM];          // fp16(Bt[l][e'][d])
__device__ __align__(256) float g_bc[16*DIM];

__device__ __forceinline__ uint32_t smem_u32(const void* p){
    uint32_t a;
    asm("{ .reg .u64 t; cvta.to.shared.u64 t, %1; cvt.u32.u64 %0, t; }" : "=r"(a) : "l"(p));
    return a;
}
#define SWZ64(o) ((o) ^ (((o) >> 3) & 0x30))

__device__ __forceinline__ void cp_async16(uint32_t s, const void* g){
    asm volatile("cp.async.cg.shared.global [%0], [%1], 16;" :: "r"(s), "l"(g));
}
#define CP_COMMIT() asm volatile("cp.async.commit_group;" ::: "memory")
#define CP_WAIT1()  asm volatile("cp.async.wait_group 1;" ::: "memory")
#define CP_WAIT0()  asm volatile("cp.async.wait_group 0;" ::: "memory")

__device__ __forceinline__ void ldsm4(uint32_t* r, uint32_t addr){
    asm volatile("ldmatrix.sync.aligned.m8n8.x4.shared.b16 {%0,%1,%2,%3}, [%4];"
        : "=r"(r[0]), "=r"(r[1]), "=r"(r[2]), "=r"(r[3]) : "r"(addr));
}
__device__ __forceinline__ void mma16816h(float* d, const uint32_t* a, const uint32_t* b){
    asm volatile("mma.sync.aligned.m16n8k16.row.col.f32.f16.f16.f32 "
        "{%0,%1,%2,%3}, {%4,%5,%6,%7}, {%8,%9}, {%0,%1,%2,%3};"
        : "+f"(d[0]), "+f"(d[1]), "+f"(d[2]), "+f"(d[3])
        : "r"(a[0]), "r"(a[1]), "r"(a[2]), "r"(a[3]), "r"(b[0]), "r"(b[1]));
}

__device__ __forceinline__ bool lang_used(int l, const int* lang_ids, const int* dict_len, int has_dict){
    int dl = has_dict ? dict_len[0] : 32000;
    bool u = false;
#pragma unroll
    for (int i = 0; i < BZ; i++) u |= ((dl - 1 - lang_ids[i]) == l);
    return u;
}

// ---------------- prologue kernels ----------------
__global__ void split_x_kernel(const float* __restrict__ in){
    size_t i = (size_t)blockIdx.x * 256 + threadIdx.x;
    float4 v = reinterpret_cast<const float4*>(in)[i];
    uint32_t h[4];
    float f[4] = {v.x, v.y, v.z, v.w};
#pragma unroll
    for (int k = 0; k < 4; k++)
        h[k] = (uint32_t)__half_as_ushort(__float2half_rn(f[k]));
    uint2 ph; ph.x = h[0] | (h[1] << 16); ph.y = h[2] | (h[3] << 16);
    reinterpret_cast<uint2*>(g_Xh)[i] = ph;
}
// src [z][1024][1024] fp32 -> dst [z][c][r] fp16 (transpose within each z)
__global__ void transpose_half_kernel(const float* __restrict__ src0,
                                      __half* __restrict__ dst,
                                      const int* __restrict__ lang_ids,
                                      const int* __restrict__ dict_len,
                                      int has_dict, int check){
    int l = blockIdx.z;
    if (check && !lang_used(l, lang_ids, dict_len, has_dict)) return;
    __shared__ float t[32][33];
    int r0 = blockIdx.x * 32;
    int c0 = blockIdx.y * 32;
    int tx = threadIdx.x, ty = threadIdx.y;
    const float* src = src0 + ((size_t)l << 20);
#pragma unroll
    for (int j = 0; j < 32; j += 8)
        t[ty + j][tx] = src[(size_t)(r0 + ty + j) * DIM + c0 + tx];
    __syncthreads();
#pragma unroll
    for (int j = 0; j < 32; j += 8){
        float v = t[tx][ty + j];
        size_t o = ((size_t)l << 20) + (size_t)(c0 + ty + j) * DIM + r0 + tx;
        dst[o] = __float2half_rn(v);
    }
}
__global__ void __launch_bounds__(1024,1) bc_kernel(
    const float* __restrict__ W, const float* __restrict__ b_base,
    const float* __restrict__ bias,
    const int* __restrict__ lang_ids, const int* __restrict__ dict_len, int has_dict){
    int l = blockIdx.x;
    if (!lang_used(l, lang_ids, dict_len, has_dict)) return;
    __shared__ float red[1024];
    int t  = threadIdx.x & 127;
    int es = threadIdx.x >> 7;
    int e2 = blockIdx.y * 128 + t;
    const float* Wl = W + ((size_t)l << 20);
    float s = 0.f;
#pragma unroll 8
    for (int e = es*128; e < es*128 + 128; e++)
        s += b_base[e] * Wl[(size_t)e * DIM + e2];
    red[threadIdx.x] = s;
    __syncthreads();
#pragma unroll
    for (int st = 512; st >= 128; st >>= 1){
        if (threadIdx.x < st) red[threadIdx.x] += red[threadIdx.x + st];
        __syncthreads();
    }
    if (threadIdx.x < 128)
        g_bc[l * DIM + e2] = red[threadIdx.x] + bias[(size_t)l * DIM + e2];
}

// ---------------- GEMM via mma.sync fp16, fully 1-pass ----------------
// CTA tile 128x128, warp tile 64x64 (2x2), K-chunk 32, SW64, 3 stages, 128 threads.
// MODE 0: Bt[l] = Wt[l] @ Wbt^T -> g_Bc fp16 (skips unused l)
// MODE 1: out[s][bb][e'] = xh[:,bb,:] @ Bt[id]^T + bc[id]
template<int MODE>
__global__ void __launch_bounds__(128,2) gemm_kernel(
    const __half* __restrict__ A0, const __half* __restrict__ B0,
    const float* __restrict__ addvec,
    const int* __restrict__ lang_ids, const int* __restrict__ dict_len, int has_dict,
    float* __restrict__ out)
{
    extern __shared__ char smem_raw[];
    uint32_t tiles = smem_u32(smem_raw);
    int tid = threadIdx.x, wid = tid >> 5, lid = tid & 31;
    int wm = wid & 1, wn = wid >> 1;
    int nt = blockIdx.x, mt = blockIdx.y, zb = blockIdx.z;

    const __half *Asrc, *Bsrc;
    size_t rsA;
    int id = 0;
    if (MODE == 0){
        if (!lang_used(zb, lang_ids, dict_len, has_dict)) return;
        Asrc = A0 + ((size_t)zb << 20) + (size_t)mt*128*DIM;
        Bsrc = B0 + (size_t)nt*128*DIM;
        rsA = 2048;
    } else {
        int dl = has_dict ? dict_len[0] : 32000;
        id = dl - 1 - lang_ids[zb];
        Asrc = A0 + (size_t)zb*DIM + (size_t)mt*128*(BZ*DIM);
        Bsrc = B0 + ((size_t)id << 20) + (size_t)nt*128*DIM;
        rsA = (size_t)BZ*DIM*2;
    }

    auto load_stage = [&](int kc, int st){
        uint32_t sb = tiles + st * (2*TILEA);
        const char* gA = (const char*)Asrc + (size_t)kc * (KC*2);
        const char* gB = (const char*)Bsrc + (size_t)kc * (KC*2);
#pragma unroll
        for (int i = 0; i < 4; i++){
            int idx = tid + 128 * i;
            int row = idx >> 2, seg = idx & 3;
            uint32_t so = SWZ64(row*64 + seg*16);
            cp_async16(sb + so, gA + (size_t)row*rsA + seg*16);
            cp_async16(sb + TILEA + so, gB + (size_t)row*2048 + seg*16);
        }
        CP_COMMIT();
    };

    float acc[4][8][4];
#pragma unroll
    for (int a = 0; a < 4; a++)
#pragma unroll
        for (int b = 0; b < 8; b++)
#pragma unroll
            for (int c = 0; c < 4; c++) acc[a][b][c] = 0.f;

    int a_row = wm*64 + (lid & 7) + ((lid >> 3) & 1) * 8;
    int a_sg  = (lid >> 4);
    int b_row = wn*64 + (lid & 7) + (lid >> 4) * 8;
    int b_sg  = (lid >> 3) & 1;

    load_stage(0, 0); load_stage(1, 1);

    for (int kc = 0; kc < NKC; kc++){
        int st = kc % 3;
        if (kc == NKC-1) { CP_WAIT0(); } else { CP_WAIT1(); }
        __syncthreads();
        if (kc + 2 < NKC) load_stage(kc + 2, (kc + 2) % 3);

        uint32_t sb = tiles + st * (2*TILEA);
        uint32_t sA = sb, sB = sb + TILEA;
#pragma unroll
        for (int ks = 0; ks < 2; ks++){
            uint32_t ah[4][4], bh[4][4];
#pragma unroll
            for (int mi = 0; mi < 4; mi++){
                uint32_t off = SWZ64((a_row + mi*16)*64 + (ks*2 + a_sg)*16);
                ldsm4(ah[mi], sA + off);
            }
#pragma unroll
            for (int ni2 = 0; ni2 < 4; ni2++){
                uint32_t off = SWZ64((b_row + ni2*16)*64 + (ks*2 + b_sg)*16);
                ldsm4(bh[ni2], sB + off);
            }
#pragma unroll
            for (int mi = 0; mi < 4; mi++)
#pragma unroll
                for (int ni = 0; ni < 8; ni++)
                    mma16816h(acc[mi][ni], ah[mi], &bh[ni>>1][(ni&1)*2]);
        }
    }

    // epilogue
#pragma unroll
    for (int ni = 0; ni < 8; ni++){
        int col = nt*128 + wn*64 + ni*8 + (lid & 3)*2;
        float av0 = 0.f, av1 = 0.f;
        if (MODE == 1){
            av0 = addvec[(size_t)id*DIM + col];
            av1 = addvec[(size_t)id*DIM + col + 1];
        }
#pragma unroll
        for (int mi = 0; mi < 4; mi++){
#pragma unroll
            for (int h = 0; h < 2; h++){
                int gm = mt*128 + wm*64 + mi*16 + (lid >> 2) + h*8;
                float v0 = acc[mi][ni][h*2]   + av0;
                float v1 = acc[mi][ni][h*2+1] + av1;
                if (MODE == 0){
                    size_t o = ((size_t)zb << 20) + (size_t)gm*DIM + col;
                    uint32_t hv = (uint32_t)__half_as_ushort(__float2half_rn(v0))
                                | ((uint32_t)__half_as_ushort(__float2half_rn(v1)) << 16);
                    *reinterpret_cast<uint32_t*>(&g_Bc[o]) = hv;
                } else {
                    size_t o = ((size_t)gm*BZ + zb)*DIM + col;
                    float2 f2; f2.x = v0; f2.y = v1;
                    *reinterpret_cast<float2*>(&out[o]) = f2;
                }
            }
        }
    }
}

extern "C" void kernel_launch(void* const* d_in, const int* in_sizes, int n_in,
                              void* d_out, int out_size) {
    const float* x      = (const float*)d_in[0];
    const int*   lids   = (const int*)d_in[1];
    const float* W_base = (const float*)d_in[2];
    const float* b_base = (const float*)d_in[3];
    const float* W      = (const float*)d_in[4];
    const float* bias   = (const float*)d_in[5];
    const int*   dlen   = (n_in > 6) ? (const int*)d_in[6] : nullptr;
    int has_dict = (n_in > 6) ? 1 : 0;
    float* out = (float*)d_out;

    cudaFuncSetAttribute(gemm_kernel<0>, cudaFuncAttributeMaxDynamicSharedMemorySize, SMEM_G);
    cudaFuncSetAttribute(gemm_kernel<1>, cudaFuncAttributeMaxDynamicSharedMemorySize, SMEM_G);

    __half *Xh, *Wt, *Wbt, *Bc;
    float* bc;
    cudaGetSymbolAddress((void**)&Xh,  g_Xh);
    cudaGetSymbolAddress((void**)&Wt,  g_Wt);
    cudaGetSymbolAddress((void**)&Wbt, g_Wbt);
    cudaGetSymbolAddress((void**)&Bc,  g_Bc);
    cudaGetSymbolAddress((void**)&bc,  g_bc);

    split_x_kernel<<<(size_t)MROWS*DIM/4/256, 256>>>(x);
    {
        dim3 g(32, 32, 16), b(32, 8);
        transpose_half_kernel<<<g, b>>>(W, Wt, lids, dlen, has_dict, 1);
    }
    {
        dim3 g(32, 32, 1), b(32, 8);
        transpose_half_kernel<<<g, b>>>(W_base, Wbt, lids, dlen, has_dict, 0);
    }
    bc_kernel<<<dim3(16, 8), 1024>>>(W, b_base, bias, lids, dlen, has_dict);

    // Precompute (1-pass): Bt[l][e'][d] = sum_e Wt[l][e'][e] * Wbt[d][e]
    {
        dim3 g(8, 8, 16), b(128);
        gemm_kernel<0><<<g, b, SMEM_G>>>(Wt, Wbt, nullptr,
                                         lids, dlen, has_dict, nullptr);
    }
    // Main (1-pass): out[s][bb][e'] = sum_d xh[s][bb][d] * Bt[id][e'][d] + bc[id][e']
    {
        dim3 g(8, 16, 16), b(128);
        gemm_kernel<1><<<g, b, SMEM_G>>>(Xh, Bc, bc,
                                         lids, dlen, has_dict, out);
    }
}